// round 1
// baseline (speedup 1.0000x reference)
#include <cuda_runtime.h>
#include <math.h>

// ---------------------------------------------------------------------------
// GGNN session-rec pipeline, B=512, T=50, D=100, N_NODE=100000, step=1
// Stages:
//  1) h = embedding[item]                     -> g_h, z[:,200:300]
//  2) hin = h@W_in+b_in ; hout = h@W_out+b_out
//  3) a_in = adj_in@hin ; a_out = adj_out@hout -> z[:,0:200]
//  4) gates = sigmoid(z @ Ggate + gb)
//  5) z2 = [z[:,0:200], r*h]; cand = tanh(z2 @ Gcand + cb)
//  6) re_emb = u*h + (1-u)*cand
//  7) seq_h gather (alias), last_h (mask-derived last position)
//  8) seq = seq_h@w2 ; last = last_h@w1
//  9) coef = sigmoid(last+seq+nb)@v * mask ; ma = [sum coef*seq_h, last]
// 10) y1 = ma @ B_mat
// 11) logits = y1 @ embedding[1:].T   (512 x 99999)
// ---------------------------------------------------------------------------

#define BATCH 512
#define TSEQ  50
#define DIM   100
#define BT    (BATCH*TSEQ)      /* 25600 */
#define NOUT  99999

// single scratch arena (floats)
__device__ float g_scratch[39000000];

#define OFF_H     0
#define OFF_HIN   2560000
#define OFF_HOUT  5120000
#define OFF_Z     7680000      /* 25600 x 300 */
#define OFF_GATES 15360000     /* 25600 x 200 */
#define OFF_Z2    20480000     /* 25600 x 300 */
#define OFF_CAND  28160000
#define OFF_REMB  30720000
#define OFF_SEQH  33280000
#define OFF_SEQ   35840000
#define OFF_LASTH 38400000     /* 512 x 100 */
#define OFF_LAST  38451200     /* 512 x 100 */
#define OFF_MA    38502400     /* 512 x 200 */
#define OFF_Y1    38604800     /* 512 x 100 */

__device__ __forceinline__ float sigmoidf_(float x){ return 1.f/(1.f+expf(-x)); }

// --------------------------- 1) gather ------------------------------------
__global__ void k_gather(const float* __restrict__ emb, const int* __restrict__ item,
                         float* __restrict__ h, float* __restrict__ z){
  int i = blockIdx.x*256 + threadIdx.x;
  if (i >= BT*DIM) return;
  int row = i/DIM, col = i - row*DIM;
  float v = __ldg(&emb[(size_t)item[row]*DIM + col]);
  h[i] = v;
  z[row*300 + 200 + col] = v;
}

// --------------------------- 3) adjacency einsums --------------------------
// per block: one batch b. hin/hout tiles in smem (40KB), adj via L1.
__global__ void k_adj(const float* __restrict__ adj_in, const float* __restrict__ adj_out,
                      const float* __restrict__ hin, const float* __restrict__ hout,
                      float* __restrict__ z){
  __shared__ float hi[TSEQ*DIM], ho[TSEQ*DIM];
  int b = blockIdx.x, tid = threadIdx.x;
  {
    const float4* h4=(const float4*)(hin + (size_t)b*TSEQ*DIM);
    const float4* g4=(const float4*)(hout + (size_t)b*TSEQ*DIM);
    float4* hi4=(float4*)hi; float4* ho4=(float4*)ho;
    for (int i=tid;i<TSEQ*DIM/4;i+=256){ hi4[i]=h4[i]; ho4[i]=g4[i]; }
  }
  __syncthreads();
  const float4* hi4=(const float4*)hi; const float4* ho4=(const float4*)ho;
  const float* ai = adj_in  + (size_t)b*TSEQ*TSEQ;
  const float* ao = adj_out + (size_t)b*TSEQ*TSEQ;
  for (int w=tid; w<TSEQ*25; w+=256){
    int t = w/25, jq = w - t*25;
    float4 si = make_float4(0.f,0.f,0.f,0.f);
    float4 so = make_float4(0.f,0.f,0.f,0.f);
    #pragma unroll 5
    for (int s=0;s<TSEQ;s++){
      float a = __ldg(&ai[t*TSEQ+s]);
      float o = __ldg(&ao[t*TSEQ+s]);
      float4 x = hi4[s*25+jq], y = ho4[s*25+jq];
      si.x += a*x.x; si.y += a*x.y; si.z += a*x.z; si.w += a*x.w;
      so.x += o*y.x; so.y += o*y.y; so.z += o*y.z; so.w += o*y.w;
    }
    float* zr = z + (size_t)(b*TSEQ+t)*300;
    ((float4*)zr)[jq] = si;            // cols 0..99   (a_in)
    ((float4*)(zr+100))[jq] = so;      // cols 100..199 (a_out)
  }
}

// --------------------------- generic NN SGEMM ------------------------------
// C[M,N] = act(A[M,K] @ B[K,N] + bias). Requires M % 64 == 0.
// act: 0=none 1=sigmoid 2=tanh
__global__ void k_sgemm(const float* __restrict__ A, const float* __restrict__ Bm,
                        const float* __restrict__ bias, float* __restrict__ C,
                        int M, int N, int K, int act){
  __shared__ float As[16][65];   // [k][m] transposed
  __shared__ float Bs[16][65];   // [k][n]
  int tid = threadIdx.x;
  int tx = tid & 15, ty = tid >> 4;
  int m0 = blockIdx.y*64, n0 = blockIdx.x*64;
  float acc[4][4] = {};
  for (int k0=0;k0<K;k0+=16){
    for (int idx=tid; idx<1024; idx+=256){
      int m = idx>>4, k = idx&15;
      As[k][m] = (k0+k < K) ? A[(size_t)(m0+m)*K + k0+k] : 0.f;
    }
    for (int idx=tid; idx<1024; idx+=256){
      int k = idx>>6, n = idx&63;
      Bs[k][n] = (k0+k < K && n0+n < N) ? Bm[(size_t)(k0+k)*N + n0+n] : 0.f;
    }
    __syncthreads();
    #pragma unroll
    for (int kk=0;kk<16;kk++){
      float a[4], bb[4];
      #pragma unroll
      for (int i=0;i<4;i++) a[i] = As[kk][ty+16*i];
      #pragma unroll
      for (int j=0;j<4;j++) bb[j] = Bs[kk][tx+16*j];
      #pragma unroll
      for (int i=0;i<4;i++)
        #pragma unroll
        for (int j=0;j<4;j++)
          acc[i][j] += a[i]*bb[j];
    }
    __syncthreads();
  }
  #pragma unroll
  for (int j=0;j<4;j++){
    int n = n0 + tx + 16*j;
    if (n >= N) continue;
    float bv = bias ? bias[n] : 0.f;
    #pragma unroll
    for (int i=0;i<4;i++){
      int m = m0 + ty + 16*i;
      float v = acc[i][j] + bv;
      if (act==1)      v = sigmoidf_(v);
      else if (act==2) v = tanhf(v);
      C[(size_t)m*N + n] = v;
    }
  }
}

// --------------------------- 5) build z2 -----------------------------------
__global__ void k_z2(const float* __restrict__ z, const float* __restrict__ gates,
                     const float* __restrict__ h, float* __restrict__ z2){
  int i = blockIdx.x*256+threadIdx.x;
  if (i >= BT*300) return;
  int row = i/300, c = i - row*300;
  float v;
  if (c < 200) v = z[i];
  else { int j = c-200; v = gates[row*200+j]*h[row*100+j]; }  // r * h
  z2[i] = v;
}

// --------------------------- 6) GRU combine --------------------------------
__global__ void k_hnew(const float* __restrict__ h, const float* __restrict__ gates,
                       const float* __restrict__ cand, float* __restrict__ remb){
  int i = blockIdx.x*256+threadIdx.x;
  if (i >= BT*DIM) return;
  int row = i/DIM, c = i - row*DIM;
  float u = gates[row*200+100+c];
  remb[i] = u*h[i] + (1.f-u)*cand[i];
}

// --------------------------- 7) seq_h / last_h gather ----------------------
__global__ void k_seqprep(const float* __restrict__ mask, const int* __restrict__ alias,
                          const float* __restrict__ remb,
                          float* __restrict__ seqh, float* __restrict__ lasth){
  __shared__ int al[TSEQ];
  __shared__ int lid_s;
  int b = blockIdx.x, tid = threadIdx.x;   // 128 threads
  if (tid < TSEQ) al[tid] = alias[b*TSEQ+tid];
  __syncthreads();
  if (tid == 0){
    float s = 0.f;
    for (int t=0;t<TSEQ;t++) s += mask[b*TSEQ+t];
    int r = (int)(s + 0.5f) - 1;
    if (r < 0) r = 0; if (r >= TSEQ) r = TSEQ-1;
    lid_s = al[r];
  }
  __syncthreads();
  for (int i=tid;i<TSEQ*DIM;i+=128){
    int t = i/DIM, j = i - t*DIM;
    seqh[(size_t)(b*TSEQ+t)*DIM + j] = remb[(size_t)(b*TSEQ + al[t])*DIM + j];
  }
  if (tid < DIM) lasth[b*DIM+tid] = remb[(size_t)(b*TSEQ + lid_s)*DIM + tid];
}

// --------------------------- 9) attention readout --------------------------
__global__ void k_attn(const float* __restrict__ last, const float* __restrict__ seq,
                       const float* __restrict__ seqh, const float* __restrict__ nb,
                       const float* __restrict__ v, const float* __restrict__ mask,
                       float* __restrict__ ma){
  __shared__ float coef[TSEQ], ls[DIM], vs[DIM], bs[DIM];
  int b = blockIdx.x, tid = threadIdx.x;   // 256 threads = 8 warps
  if (tid < DIM){ ls[tid]=last[b*DIM+tid]; vs[tid]=v[tid]; bs[tid]=nb[tid]; }
  __syncthreads();
  int w = tid >> 5, lane = tid & 31;
  for (int t=w; t<TSEQ; t+=8){
    const float* srow = seq + (size_t)(b*TSEQ+t)*DIM;
    float p = 0.f;
    for (int j=lane; j<DIM; j+=32){
      float mv = sigmoidf_(ls[j]+srow[j]+bs[j]);
      p += mv*vs[j];
    }
    #pragma unroll
    for (int o=16;o;o>>=1) p += __shfl_xor_sync(0xffffffffu, p, o);
    if (lane==0) coef[t] = p * mask[b*TSEQ+t];
  }
  __syncthreads();
  if (tid < DIM){
    float s = 0.f;
    #pragma unroll
    for (int t=0;t<TSEQ;t++) s += coef[t]*seqh[(size_t)(b*TSEQ+t)*DIM+tid];
    ma[b*200+tid]       = s;        // session vector
    ma[b*200+100+tid]   = ls[tid];  // last = last_h @ w1
  }
}

// --------------------------- 11) logits NT GEMM ----------------------------
// out[512,99999] = Y[512,100] @ E[1:100000,100]^T
// tiles 64x64, K split 2x50, smem rows [row][k] stride 54 (conflict-free reads),
// float2 k-unroll -> 4:1 FFMA:LDS issue ratio.
__global__ void k_logits(const float* __restrict__ Y, const float* __restrict__ E,
                         float* __restrict__ out){
  const int S = 54;
  __shared__ float As[64*S];
  __shared__ float Bs[64*S];
  int tid = threadIdx.x;
  int tx = tid & 15, ty = tid >> 4;
  int m0 = blockIdx.y*64, n0 = blockIdx.x*64;
  float acc[4][4] = {};
  for (int c=0;c<2;c++){
    int k0 = c*50;
    for (int idx=tid; idx<3200; idx+=256){
      int r = idx/50, k = idx - r*50;
      As[r*S+k] = Y[(size_t)(m0+r)*100 + k0 + k];
    }
    for (int idx=tid; idx<3200; idx+=256){
      int r = idx/50, k = idx - r*50;
      int n = n0 + r;
      Bs[r*S+k] = (n < NOUT) ? E[(size_t)(n+1)*100 + k0 + k] : 0.f;
    }
    __syncthreads();
    #pragma unroll
    for (int kk=0;kk<50;kk+=2){
      float2 a[4], bb[4];
      #pragma unroll
      for (int i=0;i<4;i++) a[i]  = *(const float2*)&As[(ty+16*i)*S + kk];
      #pragma unroll
      for (int j=0;j<4;j++) bb[j] = *(const float2*)&Bs[(tx+16*j)*S + kk];
      #pragma unroll
      for (int i=0;i<4;i++)
        #pragma unroll
        for (int j=0;j<4;j++)
          acc[i][j] += a[i].x*bb[j].x + a[i].y*bb[j].y;
    }
    __syncthreads();
  }
  #pragma unroll
  for (int i=0;i<4;i++){
    int m = m0 + ty + 16*i;
    #pragma unroll
    for (int j=0;j<4;j++){
      int n = n0 + tx + 16*j;
      if (n < NOUT) out[(size_t)m*NOUT + n] = acc[i][j];
    }
  }
}

// ---------------------------------------------------------------------------
extern "C" void kernel_launch(void* const* d_in, const int* in_sizes, int n_in,
                              void* d_out, int out_size){
  const float* adj_in  = (const float*)d_in[0];
  const float* adj_out = (const float*)d_in[1];
  const float* maskp   = (const float*)d_in[2];
  const int*   item    = (const int*)d_in[3];
  const int*   alias   = (const int*)d_in[4];
  // 'step' scalar may or may not be surfaced as an input; detect by size.
  int o = (n_in >= 20 && in_sizes[5] == 1) ? 6 : 5;
  const float* emb   = (const float*)d_in[o+0];
  const float* W_in  = (const float*)d_in[o+1];
  const float* b_in  = (const float*)d_in[o+2];
  const float* W_out = (const float*)d_in[o+3];
  const float* b_out = (const float*)d_in[o+4];
  const float* Ggate = (const float*)d_in[o+5];
  const float* gb    = (const float*)d_in[o+6];
  const float* Gcand = (const float*)d_in[o+7];
  const float* cb    = (const float*)d_in[o+8];
  const float* w1    = (const float*)d_in[o+9];
  const float* w2    = (const float*)d_in[o+10];
  const float* vv    = (const float*)d_in[o+11];
  const float* nb    = (const float*)d_in[o+12];
  const float* Bmat  = (const float*)d_in[o+13];
  float* out = (float*)d_out;
  (void)out_size;

  float* sc = nullptr;
  cudaGetSymbolAddress((void**)&sc, g_scratch);
  float* h     = sc + OFF_H;
  float* hin   = sc + OFF_HIN;
  float* hout  = sc + OFF_HOUT;
  float* z     = sc + OFF_Z;
  float* gates = sc + OFF_GATES;
  float* z2    = sc + OFF_Z2;
  float* cand  = sc + OFF_CAND;
  float* remb  = sc + OFF_REMB;
  float* seqh  = sc + OFF_SEQH;
  float* seq   = sc + OFF_SEQ;
  float* lasth = sc + OFF_LASTH;
  float* lastT = sc + OFF_LAST;
  float* ma    = sc + OFF_MA;
  float* y1    = sc + OFF_Y1;

  // step == 1 (fixed by the problem); single GGNN iteration
  k_gather<<<(BT*DIM+255)/256, 256>>>(emb, item, h, z);
  k_sgemm<<<dim3(2,400),256>>>(h, W_in,  b_in,  hin,  BT, DIM, DIM, 0);
  k_sgemm<<<dim3(2,400),256>>>(h, W_out, b_out, hout, BT, DIM, DIM, 0);
  k_adj<<<BATCH,256>>>(adj_in, adj_out, hin, hout, z);
  k_sgemm<<<dim3(4,400),256>>>(z, Ggate, gb, gates, BT, 200, 300, 1);
  k_z2<<<(BT*300+255)/256, 256>>>(z, gates, h, z2);
  k_sgemm<<<dim3(2,400),256>>>(z2, Gcand, cb, cand, BT, DIM, 300, 2);
  k_hnew<<<(BT*DIM+255)/256, 256>>>(h, gates, cand, remb);
  k_seqprep<<<BATCH,128>>>(maskp, alias, remb, seqh, lasth);
  k_sgemm<<<dim3(2,400),256>>>(seqh,  w2, nullptr, seq,   BT,  DIM, DIM, 0);
  k_sgemm<<<dim3(2,8),  256>>>(lasth, w1, nullptr, lastT, 512, DIM, DIM, 0);
  k_attn<<<BATCH,256>>>(lastT, seq, seqh, nb, vv, maskp, ma);
  k_sgemm<<<dim3(2,8),  256>>>(ma, Bmat, nullptr, y1, 512, DIM, 200, 0);
  k_logits<<<dim3((NOUT+63)/64, BATCH/64), 256>>>(y1, emb, out);
}

// round 4
// speedup vs baseline: 1.1730x; 1.1730x over previous
#include <cuda_runtime.h>
#include <cuda_bf16.h>
#include <math.h>
#include <stdint.h>

// ---------------------------------------------------------------------------
// GGNN session-rec pipeline, B=512, T=50, D=100, N_NODE=100000, step=1
// R4: logits GEMM via mma.sync bf16 (3-term split); tcgen05 is not emittable
// through this harness (PTX target compute_103 lacks the 'a' features).
// ---------------------------------------------------------------------------

#define BATCH 512
#define TSEQ  50
#define DIM   100
#define BT    (BATCH*TSEQ)      /* 25600 */
#define NOUT  99999
#define EPAD  100096            /* 782*128 padded E rows */

__device__ float g_scratch[39000000];
__device__ __nv_bfloat16 g_ehi[(size_t)EPAD*128];
__device__ __nv_bfloat16 g_elo[(size_t)EPAD*128];
__device__ __nv_bfloat16 g_yhi[512*128];
__device__ __nv_bfloat16 g_ylo[512*128];

#define OFF_H     0
#define OFF_HIN   2560000
#define OFF_HOUT  5120000
#define OFF_Z     7680000
#define OFF_GATES 15360000
#define OFF_Z2    20480000
#define OFF_CAND  28160000
#define OFF_REMB  30720000
#define OFF_SEQH  33280000
#define OFF_SEQ   35840000
#define OFF_LASTH 38400000
#define OFF_LAST  38451200
#define OFF_MA    38502400
#define OFF_Y1    38604800

__device__ __forceinline__ float sigmoidf_(float x){ return 1.f/(1.f+expf(-x)); }

// --------------------------- 1) gather ------------------------------------
__global__ void k_gather(const float* __restrict__ emb, const int* __restrict__ item,
                         float* __restrict__ h, float* __restrict__ z){
  int i = blockIdx.x*256 + threadIdx.x;
  if (i >= BT*DIM) return;
  int row = i/DIM, col = i - row*DIM;
  float v = __ldg(&emb[(size_t)item[row]*DIM + col]);
  h[i] = v;
  z[row*300 + 200 + col] = v;
}

// --------------------------- E / Y bf16 split ------------------------------
__global__ void k_split_e(const float* __restrict__ emb,
                          __nv_bfloat16* __restrict__ ehi, __nv_bfloat16* __restrict__ elo){
  size_t i = (size_t)blockIdx.x*256 + threadIdx.x;
  if (i >= (size_t)EPAD*128) return;
  int r = (int)(i>>7), c = (int)(i&127);
  float v = 0.f;
  if (r < NOUT && c < DIM) v = emb[(size_t)(r+1)*DIM + c];
  __nv_bfloat16 h = __float2bfloat16(v);
  ehi[i] = h;
  elo[i] = __float2bfloat16(v - __bfloat162float(h));
}
__global__ void k_split_y(const float* __restrict__ y1,
                          __nv_bfloat16* __restrict__ yhi, __nv_bfloat16* __restrict__ ylo){
  int i = blockIdx.x*256 + threadIdx.x;
  if (i >= 512*128) return;
  int r = i>>7, c = i&127;
  float v = (c < DIM) ? y1[r*DIM + c] : 0.f;
  __nv_bfloat16 h = __float2bfloat16(v);
  yhi[i] = h;
  ylo[i] = __float2bfloat16(v - __bfloat162float(h));
}

// --------------------------- 3) adjacency einsums --------------------------
__global__ void k_adj(const float* __restrict__ adj_in, const float* __restrict__ adj_out,
                      const float* __restrict__ hin, const float* __restrict__ hout,
                      float* __restrict__ z){
  extern __shared__ float sm[];
  float* hi = sm;            // 5000
  float* ho = sm + 5000;     // 5000
  float* ai = sm + 10000;    // 2500
  float* ao = sm + 12500;    // 2500
  int b = blockIdx.x, tid = threadIdx.x;
  {
    const float4* h4=(const float4*)(hin + (size_t)b*TSEQ*DIM);
    const float4* g4=(const float4*)(hout + (size_t)b*TSEQ*DIM);
    float4* hi4=(float4*)hi; float4* ho4=(float4*)ho;
    for (int i=tid;i<1250;i+=256){ hi4[i]=h4[i]; ho4[i]=g4[i]; }
    const float4* a4=(const float4*)(adj_in  + (size_t)b*2500);
    const float4* o4=(const float4*)(adj_out + (size_t)b*2500);
    float4* ai4=(float4*)ai; float4* ao4=(float4*)ao;
    for (int i=tid;i<625;i+=256){ ai4[i]=a4[i]; ao4[i]=o4[i]; }
  }
  __syncthreads();
  const float4* hi4=(const float4*)hi; const float4* ho4=(const float4*)ho;
  for (int w=tid; w<TSEQ*25; w+=256){
    int t = w/25, jq = w - t*25;
    float4 si = make_float4(0.f,0.f,0.f,0.f);
    float4 so = make_float4(0.f,0.f,0.f,0.f);
    #pragma unroll 10
    for (int s=0;s<TSEQ;s++){
      float a = ai[t*TSEQ+s];
      float o = ao[t*TSEQ+s];
      float4 x = hi4[s*25+jq], y = ho4[s*25+jq];
      si.x += a*x.x; si.y += a*x.y; si.z += a*x.z; si.w += a*x.w;
      so.x += o*y.x; so.y += o*y.y; so.z += o*y.z; so.w += o*y.w;
    }
    float* zr = z + (size_t)(b*TSEQ+t)*300;
    ((float4*)zr)[jq] = si;
    ((float4*)(zr+100))[jq] = so;
  }
}

// --------------------------- generic NN SGEMM ------------------------------
__global__ void k_sgemm(const float* __restrict__ A, const float* __restrict__ Bm,
                        const float* __restrict__ bias, float* __restrict__ C,
                        int M, int N, int K, int act){
  __shared__ float As[16][65];
  __shared__ float Bs[16][65];
  int tid = threadIdx.x;
  int tx = tid & 15, ty = tid >> 4;
  int m0 = blockIdx.y*64, n0 = blockIdx.x*64;
  float acc[4][4] = {};
  for (int k0=0;k0<K;k0+=16){
    for (int idx=tid; idx<1024; idx+=256){
      int m = idx>>4, k = idx&15;
      As[k][m] = (k0+k < K) ? A[(size_t)(m0+m)*K + k0+k] : 0.f;
    }
    for (int idx=tid; idx<1024; idx+=256){
      int k = idx>>6, n = idx&63;
      Bs[k][n] = (k0+k < K && n0+n < N) ? Bm[(size_t)(k0+k)*N + n0+n] : 0.f;
    }
    __syncthreads();
    #pragma unroll
    for (int kk=0;kk<16;kk++){
      float a[4], bb[4];
      #pragma unroll
      for (int i=0;i<4;i++) a[i] = As[kk][ty+16*i];
      #pragma unroll
      for (int j=0;j<4;j++) bb[j] = Bs[kk][tx+16*j];
      #pragma unroll
      for (int i=0;i<4;i++)
        #pragma unroll
        for (int j=0;j<4;j++)
          acc[i][j] += a[i]*bb[j];
    }
    __syncthreads();
  }
  #pragma unroll
  for (int j=0;j<4;j++){
    int n = n0 + tx + 16*j;
    if (n >= N) continue;
    float bv = bias ? bias[n] : 0.f;
    #pragma unroll
    for (int i=0;i<4;i++){
      int m = m0 + ty + 16*i;
      float v = acc[i][j] + bv;
      if (act==1)      v = sigmoidf_(v);
      else if (act==2) v = tanhf(v);
      C[(size_t)m*N + n] = v;
    }
  }
}

// --------------------------- 5/6) GRU pieces -------------------------------
__global__ void k_z2(const float* __restrict__ z, const float* __restrict__ gates,
                     const float* __restrict__ h, float* __restrict__ z2){
  int i = blockIdx.x*256+threadIdx.x;
  if (i >= BT*300) return;
  int row = i/300, c = i - row*300;
  float v;
  if (c < 200) v = z[i];
  else { int j = c-200; v = gates[row*200+j]*h[row*100+j]; }
  z2[i] = v;
}
__global__ void k_hnew(const float* __restrict__ h, const float* __restrict__ gates,
                       const float* __restrict__ cand, float* __restrict__ remb){
  int i = blockIdx.x*256+threadIdx.x;
  if (i >= BT*DIM) return;
  int row = i/DIM, c = i - row*DIM;
  float u = gates[row*200+100+c];
  remb[i] = u*h[i] + (1.f-u)*cand[i];
}

// --------------------------- 7) seq_h / last_h gather ----------------------
__global__ void k_seqprep(const float* __restrict__ mask, const int* __restrict__ alias,
                          const float* __restrict__ remb,
                          float* __restrict__ seqh, float* __restrict__ lasth){
  __shared__ int al[TSEQ];
  __shared__ int lid_s;
  int b = blockIdx.x, tid = threadIdx.x;
  if (tid < TSEQ) al[tid] = alias[b*TSEQ+tid];
  __syncthreads();
  if (tid == 0){
    float s = 0.f;
    for (int t=0;t<TSEQ;t++) s += mask[b*TSEQ+t];
    int r = (int)(s + 0.5f) - 1;
    if (r < 0) r = 0; if (r >= TSEQ) r = TSEQ-1;
    lid_s = al[r];
  }
  __syncthreads();
  for (int i=tid;i<TSEQ*DIM;i+=128){
    int t = i/DIM, j = i - t*DIM;
    seqh[(size_t)(b*TSEQ+t)*DIM + j] = remb[(size_t)(b*TSEQ + al[t])*DIM + j];
  }
  if (tid < DIM) lasth[b*DIM+tid] = remb[(size_t)(b*TSEQ + lid_s)*DIM + tid];
}

// --------------------------- 9) attention readout --------------------------
__global__ void k_attn(const float* __restrict__ last, const float* __restrict__ seq,
                       const float* __restrict__ seqh, const float* __restrict__ nb,
                       const float* __restrict__ v, const float* __restrict__ mask,
                       float* __restrict__ ma){
  __shared__ float coef[TSEQ], ls[DIM], vs[DIM], bs[DIM];
  int b = blockIdx.x, tid = threadIdx.x;
  if (tid < DIM){ ls[tid]=last[b*DIM+tid]; vs[tid]=v[tid]; bs[tid]=nb[tid]; }
  __syncthreads();
  int w = tid >> 5, lane = tid & 31;
  for (int t=w; t<TSEQ; t+=8){
    const float* srow = seq + (size_t)(b*TSEQ+t)*DIM;
    float p = 0.f;
    for (int j=lane; j<DIM; j+=32){
      float mv = sigmoidf_(ls[j]+srow[j]+bs[j]);
      p += mv*vs[j];
    }
    #pragma unroll
    for (int o=16;o;o>>=1) p += __shfl_xor_sync(0xffffffffu, p, o);
    if (lane==0) coef[t] = p * mask[b*TSEQ+t];
  }
  __syncthreads();
  if (tid < DIM){
    float s = 0.f;
    #pragma unroll
    for (int t=0;t<TSEQ;t++) s += coef[t]*seqh[(size_t)(b*TSEQ+t)*DIM+tid];
    ma[b*200+tid]       = s;
    ma[b*200+100+tid]   = ls[tid];
  }
}

// --------------------------- 11) logits via mma.sync -----------------------
// out[y, e] = Y[y,:] . E[e,:], 3-term bf16 split.
// Block tile: 128(y) x 128(e), K=128 in smem. 8 warps: warp = 32(y) x 64(e).
// Smem tiles stride S=136 bf16 (S/2 = 68 == 4 mod 32 -> all fragment LDS
// patterns touch 32 distinct banks).
#define LS 136
#define LTILE_B (128*LS*2)               /* 34816 bytes per tile */
#define LOGITS_SMEM (4*LTILE_B)          /* 139264 */

__device__ __forceinline__ void mma16816(float* d, uint32_t a0, uint32_t a1,
                                         uint32_t a2, uint32_t a3,
                                         uint32_t b0, uint32_t b1){
  asm volatile("mma.sync.aligned.m16n8k16.row.col.f32.bf16.bf16.f32 "
               "{%0,%1,%2,%3}, {%4,%5,%6,%7}, {%8,%9}, {%0,%1,%2,%3};"
               : "+f"(d[0]), "+f"(d[1]), "+f"(d[2]), "+f"(d[3])
               : "r"(a0), "r"(a1), "r"(a2), "r"(a3), "r"(b0), "r"(b1));
}
__device__ __forceinline__ uint32_t lds32(const __nv_bfloat16* p){
  return *(const uint32_t*)p;
}

__global__ void __launch_bounds__(256, 1) k_logits_mma(
    const __nv_bfloat16* __restrict__ Ehi, const __nv_bfloat16* __restrict__ Elo,
    const __nv_bfloat16* __restrict__ Yhi, const __nv_bfloat16* __restrict__ Ylo,
    float* __restrict__ out){
  extern __shared__ __nv_bfloat16 smb[];
  __nv_bfloat16* sYh = smb;
  __nv_bfloat16* sYl = smb + 128*LS;
  __nv_bfloat16* sEh = smb + 2*128*LS;
  __nv_bfloat16* sEl = smb + 3*128*LS;

  int tid = threadIdx.x;
  int e0 = blockIdx.x*128;
  int y0 = blockIdx.y*128;

  // stage tiles: thread i -> row i>>4, 16B chunk i&15, 8 row-steps
  {
    int r = tid >> 4, c16 = tid & 15;
    #pragma unroll
    for (int s=0; s<8; s++){
      int row = r + s*16;
      const uint4* gy_h = (const uint4*)(Yhi + (size_t)(y0+row)*128) + c16;
      const uint4* gy_l = (const uint4*)(Ylo + (size_t)(y0+row)*128) + c16;
      const uint4* ge_h = (const uint4*)(Ehi + (size_t)(e0+row)*128) + c16;
      const uint4* ge_l = (const uint4*)(Elo + (size_t)(e0+row)*128) + c16;
      *(uint4*)(sYh + row*LS + c16*8) = *gy_h;
      *(uint4*)(sYl + row*LS + c16*8) = *gy_l;
      *(uint4*)(sEh + row*LS + c16*8) = *ge_h;
      *(uint4*)(sEl + row*LS + c16*8) = *ge_l;
    }
  }
  __syncthreads();

  int wid = tid >> 5, lane = tid & 31;
  int wm = wid & 3;            // 4 warps along y
  int wn = wid >> 2;           // 2 warps along e
  int qr = lane >> 2;          // 0..7
  int qc = (lane & 3) * 2;     // 0,2,4,6

  float acc[2][8][4];
  #pragma unroll
  for (int mt=0;mt<2;mt++)
    #pragma unroll
    for (int nt=0;nt<8;nt++)
      #pragma unroll
      for (int j=0;j<4;j++) acc[mt][nt][j] = 0.f;

  #pragma unroll
  for (int ks=0; ks<8; ks++){
    int kk = ks*16 + qc;
    uint32_t ah[2][4], al[2][4];
    #pragma unroll
    for (int mt=0; mt<2; mt++){
      int r = wm*32 + mt*16 + qr;
      const __nv_bfloat16* p0h = sYh + r*LS;
      const __nv_bfloat16* p1h = sYh + (r+8)*LS;
      const __nv_bfloat16* p0l = sYl + r*LS;
      const __nv_bfloat16* p1l = sYl + (r+8)*LS;
      ah[mt][0]=lds32(p0h+kk); ah[mt][1]=lds32(p1h+kk);
      ah[mt][2]=lds32(p0h+kk+8); ah[mt][3]=lds32(p1h+kk+8);
      al[mt][0]=lds32(p0l+kk); al[mt][1]=lds32(p1l+kk);
      al[mt][2]=lds32(p0l+kk+8); al[mt][3]=lds32(p1l+kk+8);
    }
    #pragma unroll
    for (int nt=0; nt<8; nt++){
      int n = wn*64 + nt*8 + qr;
      const __nv_bfloat16* pbh = sEh + n*LS + kk;
      const __nv_bfloat16* pbl = sEl + n*LS + kk;
      uint32_t bh0 = lds32(pbh), bh1 = lds32(pbh+8);
      uint32_t bl0 = lds32(pbl), bl1 = lds32(pbl+8);
      #pragma unroll
      for (int mt=0; mt<2; mt++){
        mma16816(acc[mt][nt], ah[mt][0],ah[mt][1],ah[mt][2],ah[mt][3], bh0,bh1);
        mma16816(acc[mt][nt], al[mt][0],al[mt][1],al[mt][2],al[mt][3], bh0,bh1);
        mma16816(acc[mt][nt], ah[mt][0],ah[mt][1],ah[mt][2],ah[mt][3], bl0,bl1);
      }
    }
  }

  // epilogue
  #pragma unroll
  for (int mt=0; mt<2; mt++){
    int y = y0 + wm*32 + mt*16 + qr;
    #pragma unroll
    for (int nt=0; nt<8; nt++){
      int e = e0 + wn*64 + nt*8 + qc;
      float* po = out + (size_t)y*NOUT + e;
      if (e   < NOUT){ po[0] = acc[mt][nt][0]; po[(size_t)8*NOUT] = acc[mt][nt][2]; }
      if (e+1 < NOUT){ po[1] = acc[mt][nt][1]; po[(size_t)8*NOUT+1] = acc[mt][nt][3]; }
    }
  }
}

// ---------------------------------------------------------------------------
extern "C" void kernel_launch(void* const* d_in, const int* in_sizes, int n_in,
                              void* d_out, int out_size){
  const float* adj_in  = (const float*)d_in[0];
  const float* adj_out = (const float*)d_in[1];
  const float* maskp   = (const float*)d_in[2];
  const int*   item    = (const int*)d_in[3];
  const int*   alias   = (const int*)d_in[4];
  int o = (n_in >= 20 && in_sizes[5] == 1) ? 6 : 5;
  const float* emb   = (const float*)d_in[o+0];
  const float* W_in  = (const float*)d_in[o+1];
  const float* b_in  = (const float*)d_in[o+2];
  const float* W_out = (const float*)d_in[o+3];
  const float* b_out = (const float*)d_in[o+4];
  const float* Ggate = (const float*)d_in[o+5];
  const float* gb    = (const float*)d_in[o+6];
  const float* Gcand = (const float*)d_in[o+7];
  const float* cb    = (const float*)d_in[o+8];
  const float* w1    = (const float*)d_in[o+9];
  const float* w2    = (const float*)d_in[o+10];
  const float* vv    = (const float*)d_in[o+11];
  const float* nb    = (const float*)d_in[o+12];
  const float* Bmat  = (const float*)d_in[o+13];
  float* out = (float*)d_out;
  (void)out_size;

  float* sc = nullptr;
  cudaGetSymbolAddress((void**)&sc, g_scratch);
  __nv_bfloat16 *ehi=nullptr, *elo=nullptr, *yhi=nullptr, *ylo=nullptr;
  cudaGetSymbolAddress((void**)&ehi, g_ehi);
  cudaGetSymbolAddress((void**)&elo, g_elo);
  cudaGetSymbolAddress((void**)&yhi, g_yhi);
  cudaGetSymbolAddress((void**)&ylo, g_ylo);

  float* h     = sc + OFF_H;
  float* hin   = sc + OFF_HIN;
  float* hout  = sc + OFF_HOUT;
  float* z     = sc + OFF_Z;
  float* gates = sc + OFF_GATES;
  float* z2    = sc + OFF_Z2;
  float* cand  = sc + OFF_CAND;
  float* remb  = sc + OFF_REMB;
  float* seqh  = sc + OFF_SEQH;
  float* seq   = sc + OFF_SEQ;
  float* lasth = sc + OFF_LASTH;
  float* lastT = sc + OFF_LAST;
  float* ma    = sc + OFF_MA;
  float* y1    = sc + OFF_Y1;

  cudaFuncSetAttribute(k_adj, cudaFuncAttributeMaxDynamicSharedMemorySize, 60000);
  cudaFuncSetAttribute(k_logits_mma, cudaFuncAttributeMaxDynamicSharedMemorySize, LOGITS_SMEM);

  k_split_e<<<(int)(((size_t)EPAD*128 + 255)/256), 256>>>(emb, ehi, elo);

  k_gather<<<(BT*DIM+255)/256, 256>>>(emb, item, h, z);
  k_sgemm<<<dim3(2,400),256>>>(h, W_in,  b_in,  hin,  BT, DIM, DIM, 0);
  k_sgemm<<<dim3(2,400),256>>>(h, W_out, b_out, hout, BT, DIM, DIM, 0);
  k_adj<<<BATCH,256,60000>>>(adj_in, adj_out, hin, hout, z);
  k_sgemm<<<dim3(4,400),256>>>(z, Ggate, gb, gates, BT, 200, 300, 1);
  k_z2<<<(BT*300+255)/256, 256>>>(z, gates, h, z2);
  k_sgemm<<<dim3(2,400),256>>>(z2, Gcand, cb, cand, BT, DIM, 300, 2);
  k_hnew<<<(BT*DIM+255)/256, 256>>>(h, gates, cand, remb);
  k_seqprep<<<BATCH,128>>>(maskp, alias, remb, seqh, lasth);
  k_sgemm<<<dim3(2,400),256>>>(seqh,  w2, nullptr, seq,   BT,  DIM, DIM, 0);
  k_sgemm<<<dim3(2,8),  256>>>(lasth, w1, nullptr, lastT, 512, DIM, DIM, 0);
  k_attn<<<BATCH,256>>>(lastT, seq, seqh, nb, vv, maskp, ma);
  k_sgemm<<<dim3(2,8),  256>>>(ma, Bmat, nullptr, y1, 512, DIM, 200, 0);
  k_split_y<<<256,256>>>(y1, yhi, ylo);
  k_logits_mma<<<dim3(EPAD/128, 4), 256, LOGITS_SMEM>>>(ehi, elo, yhi, ylo, out);
}

// round 5
// speedup vs baseline: 1.4857x; 1.2665x over previous
#include <cuda_runtime.h>
#include <cuda_bf16.h>
#include <math.h>
#include <stdint.h>

// ---------------------------------------------------------------------------
// GGNN session-rec pipeline, B=512, T=50, D=100, N_NODE=100000, step=1
// R5: ALL big GEMMs on mma.sync bf16 3-term split (logits + hio/gates/cand/seq)
// ---------------------------------------------------------------------------

#define BATCH 512
#define TSEQ  50
#define DIM   100
#define BT    (BATCH*TSEQ)      /* 25600 */
#define NOUT  99999
#define EPAD  100096            /* 782*128 padded E rows */

__device__ float g_scratch[39000000];
__device__ __nv_bfloat16 g_ehi[(size_t)EPAD*128];
__device__ __nv_bfloat16 g_elo[(size_t)EPAD*128];
__device__ __nv_bfloat16 g_yhi[512*128];
__device__ __nv_bfloat16 g_ylo[512*128];
__device__ __nv_bfloat16 g_ashi[(size_t)BT*320];
__device__ __nv_bfloat16 g_aslo[(size_t)BT*320];
__device__ __nv_bfloat16 g_whi[172032];
__device__ __nv_bfloat16 g_wlo[172032];

// weight arena offsets (bf16 elements)
#define WO_HIO  0        /* 256 x 128 */
#define WO_GATE 32768    /* 256 x 320 */
#define WO_CAND 114688   /* 128 x 320 */
#define WO_SEQ  155648   /* 128 x 128 */

#define OFF_H     0
#define OFF_HIO   2560000      /* 25600 x 200 */
#define OFF_Z     7680000      /* 25600 x 300 */
#define OFF_GATES 15360000     /* 25600 x 200 */
#define OFF_CAND  28160000
#define OFF_REMB  30720000
#define OFF_SEQH  33280000
#define OFF_SEQ   35840000
#define OFF_LASTH 38400000
#define OFF_LAST  38451200
#define OFF_MA    38502400
#define OFF_Y1    38604800
#define OFF_BIO   38656000     /* 200 combined bias */

__device__ __forceinline__ float sigmoidf_(float x){ return 1.f/(1.f+expf(-x)); }

// --------------------------- 1) gather ------------------------------------
__global__ void k_gather(const float* __restrict__ emb, const int* __restrict__ item,
                         float* __restrict__ h, float* __restrict__ z){
  int i = blockIdx.x*256 + threadIdx.x;
  if (i >= BT*DIM) return;
  int row = i/DIM, col = i - row*DIM;
  float v = __ldg(&emb[(size_t)item[row]*DIM + col]);
  h[i] = v;
  z[row*300 + 200 + col] = v;
}

// --------------------------- bf16 split kernels ----------------------------
__global__ void k_split_e(const float* __restrict__ emb,
                          __nv_bfloat16* __restrict__ ehi, __nv_bfloat16* __restrict__ elo){
  size_t i = (size_t)blockIdx.x*256 + threadIdx.x;
  if (i >= (size_t)EPAD*128) return;
  int r = (int)(i>>7), c = (int)(i&127);
  float v = 0.f;
  if (r < NOUT && c < DIM) v = emb[(size_t)(r+1)*DIM + c];
  __nv_bfloat16 h = __float2bfloat16(v);
  ehi[i] = h;
  elo[i] = __float2bfloat16(v - __bfloat162float(h));
}
__global__ void k_split_y(const float* __restrict__ y1,
                          __nv_bfloat16* __restrict__ yhi, __nv_bfloat16* __restrict__ ylo){
  int i = blockIdx.x*256 + threadIdx.x;
  if (i >= 512*128) return;
  int r = i>>7, c = i&127;
  float v = (c < DIM) ? y1[r*DIM + c] : 0.f;
  __nv_bfloat16 h = __float2bfloat16(v);
  yhi[i] = h;
  ylo[i] = __float2bfloat16(v - __bfloat162float(h));
}
// generic A split: A (BT x K) -> (BT x Kp) hi/lo, zero pad
__global__ void k_split_a(const float* __restrict__ A,
                          __nv_bfloat16* __restrict__ hi, __nv_bfloat16* __restrict__ lo,
                          int K, int Kp){
  size_t i = (size_t)blockIdx.x*256 + threadIdx.x;
  if (i >= (size_t)BT*Kp) return;
  int r = (int)(i/Kp), c = (int)(i - (size_t)r*Kp);
  float v = (c < K) ? A[(size_t)r*K + c] : 0.f;
  __nv_bfloat16 h = __float2bfloat16(v);
  hi[i] = h;
  lo[i] = __float2bfloat16(v - __bfloat162float(h));
}
// z2 split: cols 0..199 = z, 200..299 = gates[:, c-200] * z[:, c] (h part of z)
__global__ void k_split_z2(const float* __restrict__ z, const float* __restrict__ gates,
                           __nv_bfloat16* __restrict__ hi, __nv_bfloat16* __restrict__ lo){
  size_t i = (size_t)blockIdx.x*256 + threadIdx.x;
  if (i >= (size_t)BT*320) return;
  int r = (int)(i/320), c = (int)(i - (size_t)r*320);
  float v = 0.f;
  if (c < 200)      v = z[(size_t)r*300 + c];
  else if (c < 300) v = gates[(size_t)r*200 + (c-200)] * z[(size_t)r*300 + c];
  __nv_bfloat16 h = __float2bfloat16(v);
  hi[i] = h;
  lo[i] = __float2bfloat16(v - __bfloat162float(h));
}
// weight split+transpose: W1 (K x N1) [, W2 (K x N2)] -> Wt (Np x Kp) hi/lo
__global__ void k_split_w(const float* __restrict__ W1, const float* __restrict__ W2,
                          __nv_bfloat16* __restrict__ hi, __nv_bfloat16* __restrict__ lo,
                          int K, int N1, int N2, int Kp, int Np){
  int i = blockIdx.x*256 + threadIdx.x;
  if (i >= Np*Kp) return;
  int n = i/Kp, k = i - n*Kp;
  float v = 0.f;
  if (k < K){
    if (n < N1) v = W1[(size_t)k*N1 + n];
    else if (n < N1+N2) v = W2[(size_t)k*N2 + (n-N1)];
  }
  __nv_bfloat16 h = __float2bfloat16(v);
  hi[i] = h;
  lo[i] = __float2bfloat16(v - __bfloat162float(h));
}
__global__ void k_cat_bias(const float* __restrict__ b1, const float* __restrict__ b2,
                           float* __restrict__ dst){
  int i = threadIdx.x;
  if (i < 100) dst[i] = b1[i];
  else if (i < 200) dst[i] = b2[i-100];
}

// --------------------------- 3) adjacency einsums --------------------------
// hio layout: (BT x 200), cols 0..99 = hin, 100..199 = hout
__global__ void k_adj(const float* __restrict__ adj_in, const float* __restrict__ adj_out,
                      const float* __restrict__ hio, float* __restrict__ z){
  extern __shared__ float sm[];
  float* hb = sm;            // 10000
  float* ai = sm + 10000;    // 2500
  float* ao = sm + 12500;    // 2500
  int b = blockIdx.x, tid = threadIdx.x;
  {
    const float4* h4=(const float4*)(hio + (size_t)b*TSEQ*200);
    float4* hb4=(float4*)hb;
    for (int i=tid;i<2500;i+=256) hb4[i]=h4[i];
    const float4* a4=(const float4*)(adj_in  + (size_t)b*2500);
    const float4* o4=(const float4*)(adj_out + (size_t)b*2500);
    float4* ai4=(float4*)ai; float4* ao4=(float4*)ao;
    for (int i=tid;i<625;i+=256){ ai4[i]=a4[i]; ao4[i]=o4[i]; }
  }
  __syncthreads();
  const float4* hb4=(const float4*)hb;
  for (int w=tid; w<TSEQ*25; w+=256){
    int t = w/25, jq = w - t*25;
    float4 si = make_float4(0.f,0.f,0.f,0.f);
    float4 so = make_float4(0.f,0.f,0.f,0.f);
    #pragma unroll 10
    for (int s=0;s<TSEQ;s++){
      float a = ai[t*TSEQ+s];
      float o = ao[t*TSEQ+s];
      float4 x = hb4[s*50+jq], y = hb4[s*50+25+jq];
      si.x += a*x.x; si.y += a*x.y; si.z += a*x.z; si.w += a*x.w;
      so.x += o*y.x; so.y += o*y.y; so.z += o*y.z; so.w += o*y.w;
    }
    float* zr = z + (size_t)(b*TSEQ+t)*300;
    ((float4*)zr)[jq] = si;
    ((float4*)(zr+100))[jq] = so;
  }
}

// --------------------------- small FFMA SGEMM ------------------------------
__global__ void k_sgemm(const float* __restrict__ A, const float* __restrict__ Bm,
                        const float* __restrict__ bias, float* __restrict__ C,
                        int M, int N, int K, int act){
  __shared__ float As[16][65];
  __shared__ float Bs[16][65];
  int tid = threadIdx.x;
  int tx = tid & 15, ty = tid >> 4;
  int m0 = blockIdx.y*64, n0 = blockIdx.x*64;
  float acc[4][4] = {};
  for (int k0=0;k0<K;k0+=16){
    for (int idx=tid; idx<1024; idx+=256){
      int m = idx>>4, k = idx&15;
      As[k][m] = (k0+k < K) ? A[(size_t)(m0+m)*K + k0+k] : 0.f;
    }
    for (int idx=tid; idx<1024; idx+=256){
      int k = idx>>6, n = idx&63;
      Bs[k][n] = (k0+k < K && n0+n < N) ? Bm[(size_t)(k0+k)*N + n0+n] : 0.f;
    }
    __syncthreads();
    #pragma unroll
    for (int kk=0;kk<16;kk++){
      float a[4], bb[4];
      #pragma unroll
      for (int i=0;i<4;i++) a[i] = As[kk][ty+16*i];
      #pragma unroll
      for (int j=0;j<4;j++) bb[j] = Bs[kk][tx+16*j];
      #pragma unroll
      for (int i=0;i<4;i++)
        #pragma unroll
        for (int j=0;j<4;j++)
          acc[i][j] += a[i]*bb[j];
    }
    __syncthreads();
  }
  #pragma unroll
  for (int j=0;j<4;j++){
    int n = n0 + tx + 16*j;
    if (n >= N) continue;
    float bv = bias ? bias[n] : 0.f;
    #pragma unroll
    for (int i=0;i<4;i++){
      int m = m0 + ty + 16*i;
      float v = acc[i][j] + bv;
      if (act==1)      v = sigmoidf_(v);
      else if (act==2) v = tanhf(v);
      C[(size_t)m*N + n] = v;
    }
  }
}

// --------------------------- GRU combine -----------------------------------
__global__ void k_hnew(const float* __restrict__ h, const float* __restrict__ gates,
                       const float* __restrict__ cand, float* __restrict__ remb){
  int i = blockIdx.x*256+threadIdx.x;
  if (i >= BT*DIM) return;
  int row = i/DIM, c = i - row*DIM;
  float u = gates[row*200+100+c];
  remb[i] = u*h[i] + (1.f-u)*cand[i];
}

// --------------------------- seq_h / last_h gather -------------------------
__global__ void k_seqprep(const float* __restrict__ mask, const int* __restrict__ alias,
                          const float* __restrict__ remb,
                          float* __restrict__ seqh, float* __restrict__ lasth){
  __shared__ int al[TSEQ];
  __shared__ int lid_s;
  int b = blockIdx.x, tid = threadIdx.x;
  if (tid < TSEQ) al[tid] = alias[b*TSEQ+tid];
  __syncthreads();
  if (tid == 0){
    float s = 0.f;
    for (int t=0;t<TSEQ;t++) s += mask[b*TSEQ+t];
    int r = (int)(s + 0.5f) - 1;
    if (r < 0) r = 0; if (r >= TSEQ) r = TSEQ-1;
    lid_s = al[r];
  }
  __syncthreads();
  for (int i=tid;i<TSEQ*DIM;i+=128){
    int t = i/DIM, j = i - t*DIM;
    seqh[(size_t)(b*TSEQ+t)*DIM + j] = remb[(size_t)(b*TSEQ + al[t])*DIM + j];
  }
  if (tid < DIM) lasth[b*DIM+tid] = remb[(size_t)(b*TSEQ + lid_s)*DIM + tid];
}

// --------------------------- attention readout -----------------------------
__global__ void k_attn(const float* __restrict__ last, const float* __restrict__ seq,
                       const float* __restrict__ seqh, const float* __restrict__ nb,
                       const float* __restrict__ v, const float* __restrict__ mask,
                       float* __restrict__ ma){
  __shared__ float coef[TSEQ], ls[DIM], vs[DIM], bs[DIM];
  int b = blockIdx.x, tid = threadIdx.x;
  if (tid < DIM){ ls[tid]=last[b*DIM+tid]; vs[tid]=v[tid]; bs[tid]=nb[tid]; }
  __syncthreads();
  int w = tid >> 5, lane = tid & 31;
  for (int t=w; t<TSEQ; t+=8){
    const float* srow = seq + (size_t)(b*TSEQ+t)*DIM;
    float p = 0.f;
    for (int j=lane; j<DIM; j+=32){
      float mv = sigmoidf_(ls[j]+srow[j]+bs[j]);
      p += mv*vs[j];
    }
    #pragma unroll
    for (int o=16;o;o>>=1) p += __shfl_xor_sync(0xffffffffu, p, o);
    if (lane==0) coef[t] = p * mask[b*TSEQ+t];
  }
  __syncthreads();
  if (tid < DIM){
    float s = 0.f;
    #pragma unroll
    for (int t=0;t<TSEQ;t++) s += coef[t]*seqh[(size_t)(b*TSEQ+t)*DIM+tid];
    ma[b*200+tid]       = s;
    ma[b*200+100+tid]   = ls[tid];
  }
}

// --------------------------- mma.sync helpers ------------------------------
__device__ __forceinline__ void mma16816(float* d, uint32_t a0, uint32_t a1,
                                         uint32_t a2, uint32_t a3,
                                         uint32_t b0, uint32_t b1){
  asm volatile("mma.sync.aligned.m16n8k16.row.col.f32.bf16.bf16.f32 "
               "{%0,%1,%2,%3}, {%4,%5,%6,%7}, {%8,%9}, {%0,%1,%2,%3};"
               : "+f"(d[0]), "+f"(d[1]), "+f"(d[2]), "+f"(d[3])
               : "r"(a0), "r"(a1), "r"(a2), "r"(a3), "r"(b0), "r"(b1));
}
__device__ __forceinline__ uint32_t lds32(const __nv_bfloat16* p){
  return *(const uint32_t*)p;
}

// --------------------------- generic tc GEMM -------------------------------
// C[BT, Nact] = act(A @ Wt^T + bias); A split hi/lo (BT x Kp), Wt split (Np x Kp)
// tile 128x128, K chunks of 64 staged in smem (stride 72 bf16 -> conflict-free)
#define LS2 72
#define GEMM_SMEM (4*128*LS2*2)   /* 73728 bytes */

__global__ void __launch_bounds__(256, 1) k_gemm_tc(
    const __nv_bfloat16* __restrict__ Ahi, const __nv_bfloat16* __restrict__ Alo,
    const __nv_bfloat16* __restrict__ Whi, const __nv_bfloat16* __restrict__ Wlo,
    const float* __restrict__ bias, float* __restrict__ C,
    int Nact, int Kp, int act){
  extern __shared__ __nv_bfloat16 smg[];
  __nv_bfloat16* sAh = smg;
  __nv_bfloat16* sAl = smg + 128*LS2;
  __nv_bfloat16* sWh = smg + 2*128*LS2;
  __nv_bfloat16* sWl = smg + 3*128*LS2;
  int tid = threadIdx.x;
  int n0 = blockIdx.x*128, y0 = blockIdx.y*128;
  int wid = tid>>5, lane = tid&31;
  int wm = wid&3, wn = wid>>2;
  int qr = lane>>2, qc = (lane&3)*2;

  float acc[2][8][4];
  #pragma unroll
  for (int mt=0;mt<2;mt++)
    #pragma unroll
    for (int nt=0;nt<8;nt++)
      #pragma unroll
      for (int j=0;j<4;j++) acc[mt][nt][j]=0.f;

  int nchunk = Kp >> 6;
  for (int kc=0; kc<nchunk; kc++){
    #pragma unroll
    for (int s=0;s<4;s++){
      int idx = s*256+tid;
      int row = idx>>3, c16 = idx&7;
      size_t gA = (size_t)(y0+row)*Kp + kc*64 + c16*8;
      size_t gW = (size_t)(n0+row)*Kp + kc*64 + c16*8;
      *(uint4*)(sAh + row*LS2 + c16*8) = *(const uint4*)(Ahi + gA);
      *(uint4*)(sAl + row*LS2 + c16*8) = *(const uint4*)(Alo + gA);
      *(uint4*)(sWh + row*LS2 + c16*8) = *(const uint4*)(Whi + gW);
      *(uint4*)(sWl + row*LS2 + c16*8) = *(const uint4*)(Wlo + gW);
    }
    __syncthreads();
    #pragma unroll
    for (int ks=0; ks<4; ks++){
      int kk = ks*16 + qc;
      uint32_t ah[2][4], al[2][4];
      #pragma unroll
      for (int mt=0; mt<2; mt++){
        int r = wm*32 + mt*16 + qr;
        const __nv_bfloat16* p0h = sAh + r*LS2;
        const __nv_bfloat16* p1h = sAh + (r+8)*LS2;
        const __nv_bfloat16* p0l = sAl + r*LS2;
        const __nv_bfloat16* p1l = sAl + (r+8)*LS2;
        ah[mt][0]=lds32(p0h+kk); ah[mt][1]=lds32(p1h+kk);
        ah[mt][2]=lds32(p0h+kk+8); ah[mt][3]=lds32(p1h+kk+8);
        al[mt][0]=lds32(p0l+kk); al[mt][1]=lds32(p1l+kk);
        al[mt][2]=lds32(p0l+kk+8); al[mt][3]=lds32(p1l+kk+8);
      }
      #pragma unroll
      for (int nt=0; nt<8; nt++){
        int n = wn*64 + nt*8 + qr;
        const __nv_bfloat16* pbh = sWh + n*LS2 + kk;
        const __nv_bfloat16* pbl = sWl + n*LS2 + kk;
        uint32_t bh0 = lds32(pbh), bh1 = lds32(pbh+8);
        uint32_t bl0 = lds32(pbl), bl1 = lds32(pbl+8);
        #pragma unroll
        for (int mt=0; mt<2; mt++){
          mma16816(acc[mt][nt], ah[mt][0],ah[mt][1],ah[mt][2],ah[mt][3], bh0,bh1);
          mma16816(acc[mt][nt], al[mt][0],al[mt][1],al[mt][2],al[mt][3], bh0,bh1);
          mma16816(acc[mt][nt], ah[mt][0],ah[mt][1],ah[mt][2],ah[mt][3], bl0,bl1);
        }
      }
    }
    __syncthreads();
  }

  #pragma unroll
  for (int mt=0; mt<2; mt++){
    int y = y0 + wm*32 + mt*16 + qr;
    #pragma unroll
    for (int nt=0; nt<8; nt++){
      int n = n0 + wn*64 + nt*8 + qc;
      #pragma unroll
      for (int half=0; half<2; half++){
        int nn = n + half;
        if (nn >= Nact) continue;
        float bv = bias ? bias[nn] : 0.f;
        float v0 = acc[mt][nt][half]   + bv;   // row y
        float v1 = acc[mt][nt][2+half] + bv;   // row y+8
        if (act==1){ v0 = sigmoidf_(v0); v1 = sigmoidf_(v1); }
        else if (act==2){ v0 = tanhf(v0); v1 = tanhf(v1); }
        C[(size_t)y*Nact + nn] = v0;
        C[(size_t)(y+8)*Nact + nn] = v1;
      }
    }
  }
}

// --------------------------- logits tc GEMM (unchanged) --------------------
#define LS 136
#define LTILE_B (128*LS*2)
#define LOGITS_SMEM (4*LTILE_B)

__global__ void __launch_bounds__(256, 1) k_logits_mma(
    const __nv_bfloat16* __restrict__ Ehi, const __nv_bfloat16* __restrict__ Elo,
    const __nv_bfloat16* __restrict__ Yhi, const __nv_bfloat16* __restrict__ Ylo,
    float* __restrict__ out){
  extern __shared__ __nv_bfloat16 smb[];
  __nv_bfloat16* sYh = smb;
  __nv_bfloat16* sYl = smb + 128*LS;
  __nv_bfloat16* sEh = smb + 2*128*LS;
  __nv_bfloat16* sEl = smb + 3*128*LS;

  int tid = threadIdx.x;
  int e0 = blockIdx.x*128;
  int y0 = blockIdx.y*128;

  {
    int r = tid >> 4, c16 = tid & 15;
    #pragma unroll
    for (int s=0; s<8; s++){
      int row = r + s*16;
      const uint4* gy_h = (const uint4*)(Yhi + (size_t)(y0+row)*128) + c16;
      const uint4* gy_l = (const uint4*)(Ylo + (size_t)(y0+row)*128) + c16;
      const uint4* ge_h = (const uint4*)(Ehi + (size_t)(e0+row)*128) + c16;
      const uint4* ge_l = (const uint4*)(Elo + (size_t)(e0+row)*128) + c16;
      *(uint4*)(sYh + row*LS + c16*8) = *gy_h;
      *(uint4*)(sYl + row*LS + c16*8) = *gy_l;
      *(uint4*)(sEh + row*LS + c16*8) = *ge_h;
      *(uint4*)(sEl + row*LS + c16*8) = *ge_l;
    }
  }
  __syncthreads();

  int wid = tid >> 5, lane = tid & 31;
  int wm = wid & 3;
  int wn = wid >> 2;
  int qr = lane >> 2;
  int qc = (lane & 3) * 2;

  float acc[2][8][4];
  #pragma unroll
  for (int mt=0;mt<2;mt++)
    #pragma unroll
    for (int nt=0;nt<8;nt++)
      #pragma unroll
      for (int j=0;j<4;j++) acc[mt][nt][j] = 0.f;

  #pragma unroll
  for (int ks=0; ks<8; ks++){
    int kk = ks*16 + qc;
    uint32_t ah[2][4], al[2][4];
    #pragma unroll
    for (int mt=0; mt<2; mt++){
      int r = wm*32 + mt*16 + qr;
      const __nv_bfloat16* p0h = sYh + r*LS;
      const __nv_bfloat16* p1h = sYh + (r+8)*LS;
      const __nv_bfloat16* p0l = sYl + r*LS;
      const __nv_bfloat16* p1l = sYl + (r+8)*LS;
      ah[mt][0]=lds32(p0h+kk); ah[mt][1]=lds32(p1h+kk);
      ah[mt][2]=lds32(p0h+kk+8); ah[mt][3]=lds32(p1h+kk+8);
      al[mt][0]=lds32(p0l+kk); al[mt][1]=lds32(p1l+kk);
      al[mt][2]=lds32(p0l+kk+8); al[mt][3]=lds32(p1l+kk+8);
    }
    #pragma unroll
    for (int nt=0; nt<8; nt++){
      int n = wn*64 + nt*8 + qr;
      const __nv_bfloat16* pbh = sEh + n*LS + kk;
      const __nv_bfloat16* pbl = sEl + n*LS + kk;
      uint32_t bh0 = lds32(pbh), bh1 = lds32(pbh+8);
      uint32_t bl0 = lds32(pbl), bl1 = lds32(pbl+8);
      #pragma unroll
      for (int mt=0; mt<2; mt++){
        mma16816(acc[mt][nt], ah[mt][0],ah[mt][1],ah[mt][2],ah[mt][3], bh0,bh1);
        mma16816(acc[mt][nt], al[mt][0],al[mt][1],al[mt][2],al[mt][3], bh0,bh1);
        mma16816(acc[mt][nt], ah[mt][0],ah[mt][1],ah[mt][2],ah[mt][3], bl0,bl1);
      }
    }
  }

  #pragma unroll
  for (int mt=0; mt<2; mt++){
    int y = y0 + wm*32 + mt*16 + qr;
    #pragma unroll
    for (int nt=0; nt<8; nt++){
      int e = e0 + wn*64 + nt*8 + qc;
      float* po = out + (size_t)y*NOUT + e;
      if (e   < NOUT){ po[0] = acc[mt][nt][0]; po[(size_t)8*NOUT] = acc[mt][nt][2]; }
      if (e+1 < NOUT){ po[1] = acc[mt][nt][1]; po[(size_t)8*NOUT+1] = acc[mt][nt][3]; }
    }
  }
}

// ---------------------------------------------------------------------------
extern "C" void kernel_launch(void* const* d_in, const int* in_sizes, int n_in,
                              void* d_out, int out_size){
  const float* adj_in  = (const float*)d_in[0];
  const float* adj_out = (const float*)d_in[1];
  const float* maskp   = (const float*)d_in[2];
  const int*   item    = (const int*)d_in[3];
  const int*   alias   = (const int*)d_in[4];
  int o = (n_in >= 20 && in_sizes[5] == 1) ? 6 : 5;
  const float* emb   = (const float*)d_in[o+0];
  const float* W_in  = (const float*)d_in[o+1];
  const float* b_in  = (const float*)d_in[o+2];
  const float* W_out = (const float*)d_in[o+3];
  const float* b_out = (const float*)d_in[o+4];
  const float* Ggate = (const float*)d_in[o+5];
  const float* gb    = (const float*)d_in[o+6];
  const float* Gcand = (const float*)d_in[o+7];
  const float* cb    = (const float*)d_in[o+8];
  const float* w1    = (const float*)d_in[o+9];
  const float* w2    = (const float*)d_in[o+10];
  const float* vv    = (const float*)d_in[o+11];
  const float* nb    = (const float*)d_in[o+12];
  const float* Bmat  = (const float*)d_in[o+13];
  float* out = (float*)d_out;
  (void)out_size;

  float* sc = nullptr;
  cudaGetSymbolAddress((void**)&sc, g_scratch);
  __nv_bfloat16 *ehi=nullptr, *elo=nullptr, *yhi=nullptr, *ylo=nullptr;
  __nv_bfloat16 *ashi=nullptr, *aslo=nullptr, *whi=nullptr, *wlo=nullptr;
  cudaGetSymbolAddress((void**)&ehi, g_ehi);
  cudaGetSymbolAddress((void**)&elo, g_elo);
  cudaGetSymbolAddress((void**)&yhi, g_yhi);
  cudaGetSymbolAddress((void**)&ylo, g_ylo);
  cudaGetSymbolAddress((void**)&ashi, g_ashi);
  cudaGetSymbolAddress((void**)&aslo, g_aslo);
  cudaGetSymbolAddress((void**)&whi, g_whi);
  cudaGetSymbolAddress((void**)&wlo, g_wlo);

  float* h     = sc + OFF_H;
  float* hio   = sc + OFF_HIO;
  float* z     = sc + OFF_Z;
  float* gates = sc + OFF_GATES;
  float* cand  = sc + OFF_CAND;
  float* remb  = sc + OFF_REMB;
  float* seqh  = sc + OFF_SEQH;
  float* seq   = sc + OFF_SEQ;
  float* lasth = sc + OFF_LASTH;
  float* lastT = sc + OFF_LAST;
  float* ma    = sc + OFF_MA;
  float* y1    = sc + OFF_Y1;
  float* bio   = sc + OFF_BIO;

  cudaFuncSetAttribute(k_adj, cudaFuncAttributeMaxDynamicSharedMemorySize, 60000);
  cudaFuncSetAttribute(k_logits_mma, cudaFuncAttributeMaxDynamicSharedMemorySize, LOGITS_SMEM);
  cudaFuncSetAttribute(k_gemm_tc, cudaFuncAttributeMaxDynamicSharedMemorySize, GEMM_SMEM);

  // static preps (weights, E-split, combined bias)
  k_split_e<<<(int)(((size_t)EPAD*128 + 255)/256), 256>>>(emb, ehi, elo);
  k_split_w<<<(256*128+255)/256,256>>>(W_in, W_out, whi+WO_HIO, wlo+WO_HIO, 100, 100, 100, 128, 256);
  k_split_w<<<(256*320+255)/256,256>>>(Ggate, nullptr, whi+WO_GATE, wlo+WO_GATE, 300, 200, 0, 320, 256);
  k_split_w<<<(128*320+255)/256,256>>>(Gcand, nullptr, whi+WO_CAND, wlo+WO_CAND, 300, 100, 0, 320, 128);
  k_split_w<<<(128*128+255)/256,256>>>(w2, nullptr, whi+WO_SEQ, wlo+WO_SEQ, 100, 100, 0, 128, 128);
  k_cat_bias<<<1,256>>>(b_in, b_out, bio);

  // pipeline
  k_gather<<<(BT*DIM+255)/256, 256>>>(emb, item, h, z);
  k_split_a<<<(int)(((size_t)BT*128+255)/256),256>>>(h, ashi, aslo, 100, 128);
  k_gemm_tc<<<dim3(2,200),256,GEMM_SMEM>>>(ashi, aslo, whi+WO_HIO, wlo+WO_HIO, bio, hio, 200, 128, 0);
  k_adj<<<BATCH,256,60000>>>(adj_in, adj_out, hio, z);
  k_split_a<<<(int)(((size_t)BT*320+255)/256),256>>>(z, ashi, aslo, 300, 320);
  k_gemm_tc<<<dim3(2,200),256,GEMM_SMEM>>>(ashi, aslo, whi+WO_GATE, wlo+WO_GATE, gb, gates, 200, 320, 1);
  k_split_z2<<<(int)(((size_t)BT*320+255)/256),256>>>(z, gates, ashi, aslo);
  k_gemm_tc<<<dim3(1,200),256,GEMM_SMEM>>>(ashi, aslo, whi+WO_CAND, wlo+WO_CAND, cb, cand, 100, 320, 2);
  k_hnew<<<(BT*DIM+255)/256, 256>>>(h, gates, cand, remb);
  k_seqprep<<<BATCH,128>>>(maskp, alias, remb, seqh, lasth);
  k_split_a<<<(int)(((size_t)BT*128+255)/256),256>>>(seqh, ashi, aslo, 100, 128);
  k_gemm_tc<<<dim3(1,200),256,GEMM_SMEM>>>(ashi, aslo, whi+WO_SEQ, wlo+WO_SEQ, nullptr, seq, 100, 128, 0);
  k_sgemm<<<dim3(2,8),  256>>>(lasth, w1, nullptr, lastT, 512, DIM, DIM, 0);
  k_attn<<<BATCH,256>>>(lastT, seq, seqh, nb, vv, maskp, ma);
  k_sgemm<<<dim3(2,8),  256>>>(ma, Bmat, nullptr, y1, 512, DIM, 200, 0);
  k_split_y<<<256,256>>>(y1, yhi, ylo);
  k_logits_mma<<<dim3(EPAD/128, 4), 256, LOGITS_SMEM>>>(ehi, elo, yhi, ylo, out);
}

// round 7
// speedup vs baseline: 1.6027x; 1.0788x over previous
#include <cuda_runtime.h>
#include <cuda_bf16.h>
#include <math.h>
#include <stdint.h>

// ---------------------------------------------------------------------------
// GGNN session-rec, B=512, T=50, D=100, N_NODE=100000, step=1
// R6: inline fp32->bf16 hi/lo split inside all tc GEMM staging (no split
// passes), GRU combine fused into cand-GEMM epilogue, logits K-chunked for
// occupancy 2, single weight-prep kernel. 13 launches.
// ---------------------------------------------------------------------------

#define BATCH 512
#define TSEQ  50
#define DIM   100
#define BT    (BATCH*TSEQ)      /* 25600 */
#define NOUT  99999
#define EPAD  100096            /* 782*128 */

__device__ float g_scratch[26000000];
__device__ __nv_bfloat16 g_whi[172032];
__device__ __nv_bfloat16 g_wlo[172032];

// weight arena offsets (bf16 elements)
#define WO_HIO  0        /* 256 x 128 */
#define WO_GATE 32768    /* 256 x 320 */
#define WO_CAND 114688   /* 128 x 320 */
#define WO_SEQ  155648   /* 128 x 128 */

#define OFF_Z     0
#define OFF_HIO   7680000
#define OFF_GATES 12800000
#define OFF_REMB  17920000
#define OFF_SEQH  20480000
#define OFF_SEQ   23040000
#define OFF_LASTH 25600000
#define OFF_LAST  25651200
#define OFF_MA    25702400
#define OFF_Y1    25804800
#define OFF_BIO   25856000

__device__ __forceinline__ float sigmoidf_(float x){ return 1.f/(1.f+expf(-x)); }

__device__ __forceinline__ uint32_t pack_bf2(__nv_bfloat16 a, __nv_bfloat16 b){
  return ((uint32_t)__bfloat16_as_ushort(b)<<16) | (uint32_t)__bfloat16_as_ushort(a);
}
__device__ __forceinline__ void split4(float4 v, uint2& hi, uint2& lo){
  __nv_bfloat16 h0=__float2bfloat16(v.x), h1=__float2bfloat16(v.y),
                h2=__float2bfloat16(v.z), h3=__float2bfloat16(v.w);
  hi.x = pack_bf2(h0,h1); hi.y = pack_bf2(h2,h3);
  __nv_bfloat16 l0=__float2bfloat16(v.x-__bfloat162float(h0));
  __nv_bfloat16 l1=__float2bfloat16(v.y-__bfloat162float(h1));
  __nv_bfloat16 l2=__float2bfloat16(v.z-__bfloat162float(h2));
  __nv_bfloat16 l3=__float2bfloat16(v.w-__bfloat162float(h3));
  lo.x = pack_bf2(l0,l1); lo.y = pack_bf2(l2,l3);
}
__device__ __forceinline__ void mma16816(float* d, uint32_t a0, uint32_t a1,
                                         uint32_t a2, uint32_t a3,
                                         uint32_t b0, uint32_t b1){
  asm volatile("mma.sync.aligned.m16n8k16.row.col.f32.bf16.bf16.f32 "
               "{%0,%1,%2,%3}, {%4,%5,%6,%7}, {%8,%9}, {%0,%1,%2,%3};"
               : "+f"(d[0]), "+f"(d[1]), "+f"(d[2]), "+f"(d[3])
               : "r"(a0), "r"(a1), "r"(a2), "r"(a3), "r"(b0), "r"(b1));
}
__device__ __forceinline__ uint32_t lds32(const __nv_bfloat16* p){
  return *(const uint32_t*)p;
}

// --------------------------- weight prep (one launch) ----------------------
__global__ void k_prep(const float* __restrict__ W_in, const float* __restrict__ W_out,
                       const float* __restrict__ Ggate, const float* __restrict__ Gcand,
                       const float* __restrict__ w2,
                       const float* __restrict__ b_in, const float* __restrict__ b_out,
                       __nv_bfloat16* __restrict__ whi, __nv_bfloat16* __restrict__ wlo,
                       float* __restrict__ bio){
  int i = blockIdx.x*256 + threadIdx.x;
  if (i < 172032){
    float v = 0.f;
    if (i < 32768){
      int n = i>>7, k = i&127;
      if (k < 100) v = (n < 100) ? W_in[k*100+n] : W_out[k*100+(n-100)];
    } else if (i < 114688){
      int j = i-32768; int n = j/320, k = j - n*320;
      if (k < 300) v = Ggate[k*200+n];
    } else if (i < 155648){
      int j = i-114688; int n = j/320, k = j - n*320;
      if (k < 300) v = Gcand[k*100+n];
    } else {
      int j = i-155648; int n = j>>7, k = j&127;
      if (k < 100) v = w2[k*100+n];
    }
    __nv_bfloat16 h = __float2bfloat16(v);
    whi[i] = h;
    wlo[i] = __float2bfloat16(v - __bfloat162float(h));
  } else if (i < 172232){
    int j = i-172032;
    bio[j] = (j < 100) ? b_in[j] : b_out[j-100];
  }
}

// --------------------------- gather: h -> z[:,200:300] ---------------------
__global__ void k_gather(const float* __restrict__ emb, const int* __restrict__ item,
                         float* __restrict__ z){
  int i = blockIdx.x*256 + threadIdx.x;
  if (i >= BT*DIM) return;
  int row = i/DIM, col = i - row*DIM;
  z[row*300 + 200 + col] = __ldg(&emb[(size_t)item[row]*DIM + col]);
}

// --------------------------- adjacency einsums -----------------------------
__global__ void k_adj(const float* __restrict__ adj_in, const float* __restrict__ adj_out,
                      const float* __restrict__ hio, float* __restrict__ z){
  extern __shared__ float sm[];
  float* hb = sm;            // 10000
  float* ai = sm + 10000;    // 2500
  float* ao = sm + 12500;    // 2500
  int b = blockIdx.x, tid = threadIdx.x;
  {
    const float4* h4=(const float4*)(hio + (size_t)b*TSEQ*200);
    float4* hb4=(float4*)hb;
    for (int i=tid;i<2500;i+=256) hb4[i]=h4[i];
    const float4* a4=(const float4*)(adj_in  + (size_t)b*2500);
    const float4* o4=(const float4*)(adj_out + (size_t)b*2500);
    float4* ai4=(float4*)ai; float4* ao4=(float4*)ao;
    for (int i=tid;i<625;i+=256){ ai4[i]=a4[i]; ao4[i]=o4[i]; }
  }
  __syncthreads();
  const float4* hb4=(const float4*)hb;
  for (int w=tid; w<TSEQ*25; w+=256){
    int t = w/25, jq = w - t*25;
    float4 si = make_float4(0.f,0.f,0.f,0.f);
    float4 so = make_float4(0.f,0.f,0.f,0.f);
    #pragma unroll 10
    for (int s=0;s<TSEQ;s++){
      float a = ai[t*TSEQ+s];
      float o = ao[t*TSEQ+s];
      float4 x = hb4[s*50+jq], y = hb4[s*50+25+jq];
      si.x += a*x.x; si.y += a*x.y; si.z += a*x.z; si.w += a*x.w;
      so.x += o*y.x; so.y += o*y.y; so.z += o*y.z; so.w += o*y.w;
    }
    float* zr = z + (size_t)(b*TSEQ+t)*300;
    ((float4*)zr)[jq] = si;
    ((float4*)(zr+100))[jq] = so;
  }
}

// --------------------------- small FFMA SGEMM ------------------------------
__global__ void k_sgemm(const float* __restrict__ A, const float* __restrict__ Bm,
                        const float* __restrict__ bias, float* __restrict__ C,
                        int M, int N, int K, int act){
  __shared__ float As[16][65];
  __shared__ float Bs[16][65];
  int tid = threadIdx.x;
  int tx = tid & 15, ty = tid >> 4;
  int m0 = blockIdx.y*64, n0 = blockIdx.x*64;
  float acc[4][4] = {};
  for (int k0=0;k0<K;k0+=16){
    for (int idx=tid; idx<1024; idx+=256){
      int m = idx>>4, k = idx&15;
      As[k][m] = (k0+k < K) ? A[(size_t)(m0+m)*K + k0+k] : 0.f;
    }
    for (int idx=tid; idx<1024; idx+=256){
      int k = idx>>6, n = idx&63;
      Bs[k][n] = (k0+k < K && n0+n < N) ? Bm[(size_t)(k0+k)*N + n0+n] : 0.f;
    }
    __syncthreads();
    #pragma unroll
    for (int kk=0;kk<16;kk++){
      float a[4], bb[4];
      #pragma unroll
      for (int i=0;i<4;i++) a[i] = As[kk][ty+16*i];
      #pragma unroll
      for (int j=0;j<4;j++) bb[j] = Bs[kk][tx+16*j];
      #pragma unroll
      for (int i=0;i<4;i++)
        #pragma unroll
        for (int j=0;j<4;j++)
          acc[i][j] += a[i]*bb[j];
    }
    __syncthreads();
  }
  #pragma unroll
  for (int j=0;j<4;j++){
    int n = n0 + tx + 16*j;
    if (n >= N) continue;
    float bv = bias ? bias[n] : 0.f;
    #pragma unroll
    for (int i=0;i<4;i++){
      int m = m0 + ty + 16*i;
      float v = acc[i][j] + bv;
      if (act==1)      v = sigmoidf_(v);
      else if (act==2) v = tanhf(v);
      C[(size_t)m*N + n] = v;
    }
  }
}

// --------------------------- seq_h / last_h gather -------------------------
__global__ void k_seqprep(const float* __restrict__ mask, const int* __restrict__ alias,
                          const float* __restrict__ remb,
                          float* __restrict__ seqh, float* __restrict__ lasth){
  __shared__ int al[TSEQ];
  __shared__ int lid_s;
  int b = blockIdx.x, tid = threadIdx.x;
  if (tid < TSEQ) al[tid] = alias[b*TSEQ+tid];
  __syncthreads();
  if (tid == 0){
    float s = 0.f;
    for (int t=0;t<TSEQ;t++) s += mask[b*TSEQ+t];
    int r = (int)(s + 0.5f) - 1;
    if (r < 0) r = 0; if (r >= TSEQ) r = TSEQ-1;
    lid_s = al[r];
  }
  __syncthreads();
  for (int i=tid;i<TSEQ*DIM;i+=128){
    int t = i/DIM, j = i - t*DIM;
    seqh[(size_t)(b*TSEQ+t)*DIM + j] = remb[(size_t)(b*TSEQ + al[t])*DIM + j];
  }
  if (tid < DIM) lasth[b*DIM+tid] = remb[(size_t)(b*TSEQ + lid_s)*DIM + tid];
}

// --------------------------- attention readout -----------------------------
__global__ void k_attn(const float* __restrict__ last, const float* __restrict__ seq,
                       const float* __restrict__ seqh, const float* __restrict__ nb,
                       const float* __restrict__ v, const float* __restrict__ mask,
                       float* __restrict__ ma){
  __shared__ float coef[TSEQ], ls[DIM], vs[DIM], bs[DIM];
  int b = blockIdx.x, tid = threadIdx.x;
  if (tid < DIM){ ls[tid]=last[b*DIM+tid]; vs[tid]=v[tid]; bs[tid]=nb[tid]; }
  __syncthreads();
  int w = tid >> 5, lane = tid & 31;
  for (int t=w; t<TSEQ; t+=8){
    const float* srow = seq + (size_t)(b*TSEQ+t)*DIM;
    float p = 0.f;
    for (int j=lane; j<DIM; j+=32){
      float mv = sigmoidf_(ls[j]+srow[j]+bs[j]);
      p += mv*vs[j];
    }
    #pragma unroll
    for (int o=16;o;o>>=1) p += __shfl_xor_sync(0xffffffffu, p, o);
    if (lane==0) coef[t] = p * mask[b*TSEQ+t];
  }
  __syncthreads();
  if (tid < DIM){
    float s = 0.f;
    #pragma unroll
    for (int t=0;t<TSEQ;t++) s += coef[t]*seqh[(size_t)(b*TSEQ+t)*DIM+tid];
    ma[b*200+tid]       = s;
    ma[b*200+100+tid]   = ls[tid];
  }
}

// --------------------------- generic tc GEMM (inline A split) --------------
// C = epi(A' @ Wt^T + bias); A' is fp32 (inline split to hi/lo bf16),
// Wt pre-split bf16 (Np x Kp). Tile 128x128, K chunks of 64.
// amode 0: plain A (stride Astride, valid cols Ka)
// amode 1: z2 synth: cols<200 = z, 200..299 = gates*z, >=300 pad (A=z, stride 300)
// emode 0 none, 1 sigmoid, 3 GRU fuse: C = u*h + (1-u)*tanh(acc+bias)
#define LS2 72
#define GEMM_SMEM (4*128*LS2*2)   /* 73728 */

__global__ void __launch_bounds__(256) k_gemm_tc(
    const float* __restrict__ A, const float* __restrict__ Gt,
    const __nv_bfloat16* __restrict__ Whi, const __nv_bfloat16* __restrict__ Wlo,
    const float* __restrict__ bias, float* __restrict__ C,
    int Astride, int Ka, int Kp, int Nact, int amode, int emode){
  extern __shared__ __nv_bfloat16 smg[];
  __nv_bfloat16* sAh = smg;
  __nv_bfloat16* sAl = smg + 128*LS2;
  __nv_bfloat16* sWh = smg + 2*128*LS2;
  __nv_bfloat16* sWl = smg + 3*128*LS2;
  int tid = threadIdx.x;
  int n0 = blockIdx.x*128, y0 = blockIdx.y*128;
  int wid = tid>>5, lane = tid&31;
  int wm = wid&3, wn = wid>>2;
  int qr = lane>>2, qc = (lane&3)*2;

  float acc[2][8][4];
  #pragma unroll
  for (int mt=0;mt<2;mt++)
    #pragma unroll
    for (int nt=0;nt<8;nt++)
      #pragma unroll
      for (int j=0;j<4;j++) acc[mt][nt][j]=0.f;

  int nchunk = Kp >> 6;
  for (int kc=0; kc<nchunk; kc++){
    // stage A (fp32 -> hi/lo)
    #pragma unroll
    for (int s=0;s<8;s++){
      int idx = s*256+tid;
      int row = idx>>4, q = idx&15;
      int col = kc*64 + q*4;
      float4 v = make_float4(0.f,0.f,0.f,0.f);
      if (amode == 0){
        if (col < Ka) v = *(const float4*)(A + (size_t)(y0+row)*Astride + col);
      } else {
        if (col < 200) v = *(const float4*)(A + (size_t)(y0+row)*300 + col);
        else if (col < 300){
          float4 zv = *(const float4*)(A + (size_t)(y0+row)*300 + col);
          float4 gv = *(const float4*)(Gt + (size_t)(y0+row)*200 + (col-200));
          v = make_float4(zv.x*gv.x, zv.y*gv.y, zv.z*gv.z, zv.w*gv.w);
        }
      }
      uint2 hi, lo; split4(v, hi, lo);
      *(uint2*)(sAh + row*LS2 + q*4) = hi;
      *(uint2*)(sAl + row*LS2 + q*4) = lo;
    }
    // stage W (bf16 pre-split)
    #pragma unroll
    for (int s=0;s<4;s++){
      int idx = s*256+tid;
      int row = idx>>3, c8 = idx&7;
      size_t g = (size_t)(n0+row)*Kp + kc*64 + c8*8;
      *(uint4*)(sWh + row*LS2 + c8*8) = *(const uint4*)(Whi + g);
      *(uint4*)(sWl + row*LS2 + c8*8) = *(const uint4*)(Wlo + g);
    }
    __syncthreads();
    #pragma unroll
    for (int ks=0; ks<4; ks++){
      int kk = ks*16 + qc;
      uint32_t ah[2][4], al[2][4];
      #pragma unroll
      for (int mt=0; mt<2; mt++){
        int r = wm*32 + mt*16 + qr;
        const __nv_bfloat16* p0h = sAh + r*LS2;
        const __nv_bfloat16* p1h = sAh + (r+8)*LS2;
        const __nv_bfloat16* p0l = sAl + r*LS2;
        const __nv_bfloat16* p1l = sAl + (r+8)*LS2;
        ah[mt][0]=lds32(p0h+kk); ah[mt][1]=lds32(p1h+kk);
        ah[mt][2]=lds32(p0h+kk+8); ah[mt][3]=lds32(p1h+kk+8);
        al[mt][0]=lds32(p0l+kk); al[mt][1]=lds32(p1l+kk);
        al[mt][2]=lds32(p0l+kk+8); al[mt][3]=lds32(p1l+kk+8);
      }
      #pragma unroll
      for (int nt=0; nt<8; nt++){
        int n = wn*64 + nt*8 + qr;
        const __nv_bfloat16* pbh = sWh + n*LS2 + kk;
        const __nv_bfloat16* pbl = sWl + n*LS2 + kk;
        uint32_t bh0 = lds32(pbh), bh1 = lds32(pbh+8);
        uint32_t bl0 = lds32(pbl), bl1 = lds32(pbl+8);
        #pragma unroll
        for (int mt=0; mt<2; mt++){
          mma16816(acc[mt][nt], ah[mt][0],ah[mt][1],ah[mt][2],ah[mt][3], bh0,bh1);
          mma16816(acc[mt][nt], al[mt][0],al[mt][1],al[mt][2],al[mt][3], bh0,bh1);
          mma16816(acc[mt][nt], ah[mt][0],ah[mt][1],ah[mt][2],ah[mt][3], bl0,bl1);
        }
      }
    }
    __syncthreads();
  }

  #pragma unroll
  for (int mt=0; mt<2; mt++){
    int y = y0 + wm*32 + mt*16 + qr;
    #pragma unroll
    for (int nt=0; nt<8; nt++){
      #pragma unroll
      for (int half=0; half<2; half++){
        int nn = n0 + wn*64 + nt*8 + qc + half;
        if (nn >= Nact) continue;
        float bv = bias ? bias[nn] : 0.f;
        float v0 = acc[mt][nt][half]   + bv;
        float v1 = acc[mt][nt][2+half] + bv;
        if (emode==1){ v0 = sigmoidf_(v0); v1 = sigmoidf_(v1); }
        else if (emode==3){
          v0 = tanhf(v0); v1 = tanhf(v1);
          float u0 = Gt[(size_t)y*200 + 100 + nn];
          float u1 = Gt[(size_t)(y+8)*200 + 100 + nn];
          float h0 = A[(size_t)y*300 + 200 + nn];
          float h1 = A[(size_t)(y+8)*300 + 200 + nn];
          v0 = u0*h0 + (1.f-u0)*v0;
          v1 = u1*h1 + (1.f-u1)*v1;
        }
        C[(size_t)y*Nact + nn] = v0;
        C[(size_t)(y+8)*Nact + nn] = v1;
      }
    }
  }
}

// --------------------------- logits GEMM (inline both operands) ------------
// out[y, e] = Y[y,:] . E[e,:]; Y from y1 fp32 (512x100), E from emb[1:] fp32.
#define LOGITS_SMEM (4*128*LS2*2)   /* 73728 */

__global__ void __launch_bounds__(256, 2) k_logits_mma(
    const float* __restrict__ emb, const float* __restrict__ y1,
    float* __restrict__ out){
  extern __shared__ __nv_bfloat16 smb[];
  __nv_bfloat16* sYh = smb;
  __nv_bfloat16* sYl = smb + 128*LS2;
  __nv_bfloat16* sEh = smb + 2*128*LS2;
  __nv_bfloat16* sEl = smb + 3*128*LS2;

  int tid = threadIdx.x;
  int e0 = blockIdx.x*128;
  int y0 = blockIdx.y*128;
  int wid = tid>>5, lane = tid&31;
  int wm = wid&3, wn = wid>>2;
  int qr = lane>>2, qc = (lane&3)*2;

  float acc[2][8][4];
  #pragma unroll
  for (int mt=0;mt<2;mt++)
    #pragma unroll
    for (int nt=0;nt<8;nt++)
      #pragma unroll
      for (int j=0;j<4;j++) acc[mt][nt][j] = 0.f;

  #pragma unroll
  for (int kc=0; kc<2; kc++){
    #pragma unroll
    for (int s=0;s<8;s++){
      int idx = s*256+tid;
      int row = idx>>4, q = idx&15;
      int col = kc*64 + q*4;
      float4 vy = make_float4(0.f,0.f,0.f,0.f);
      if (col < 100) vy = *(const float4*)(y1 + (size_t)(y0+row)*100 + col);
      uint2 hi, lo; split4(vy, hi, lo);
      *(uint2*)(sYh + row*LS2 + q*4) = hi;
      *(uint2*)(sYl + row*LS2 + q*4) = lo;
      float4 ve = make_float4(0.f,0.f,0.f,0.f);
      int er = e0 + row;
      if (col < 100 && er < NOUT) ve = *(const float4*)(emb + (size_t)(er+1)*100 + col);
      split4(ve, hi, lo);
      *(uint2*)(sEh + row*LS2 + q*4) = hi;
      *(uint2*)(sEl + row*LS2 + q*4) = lo;
    }
    __syncthreads();
    #pragma unroll
    for (int ks=0; ks<4; ks++){
      int kk = ks*16 + qc;
      uint32_t ah[2][4], al[2][4];
      #pragma unroll
      for (int mt=0; mt<2; mt++){
        int r = wm*32 + mt*16 + qr;
        const __nv_bfloat16* p0h = sYh + r*LS2;
        const __nv_bfloat16* p1h = sYh + (r+8)*LS2;
        const __nv_bfloat16* p0l = sYl + r*LS2;
        const __nv_bfloat16* p1l = sYl + (r+8)*LS2;
        ah[mt][0]=lds32(p0h+kk); ah[mt][1]=lds32(p1h+kk);
        ah[mt][2]=lds32(p0h+kk+8); ah[mt][3]=lds32(p1h+kk+8);
        al[mt][0]=lds32(p0l+kk); al[mt][1]=lds32(p1l+kk);
        al[mt][2]=lds32(p0l+kk+8); al[mt][3]=lds32(p1l+kk+8);
      }
      #pragma unroll
      for (int nt=0; nt<8; nt++){
        int n = wn*64 + nt*8 + qr;
        const __nv_bfloat16* pbh = sEh + n*LS2 + kk;
        const __nv_bfloat16* pbl = sEl + n*LS2 + kk;
        uint32_t bh0 = lds32(pbh), bh1 = lds32(pbh+8);
        uint32_t bl0 = lds32(pbl), bl1 = lds32(pbl+8);
        #pragma unroll
        for (int mt=0; mt<2; mt++){
          mma16816(acc[mt][nt], ah[mt][0],ah[mt][1],ah[mt][2],ah[mt][3], bh0,bh1);
          mma16816(acc[mt][nt], al[mt][0],al[mt][1],al[mt][2],al[mt][3], bh0,bh1);
          mma16816(acc[mt][nt], ah[mt][0],ah[mt][1],ah[mt][2],ah[mt][3], bl0,bl1);
        }
      }
    }
    __syncthreads();
  }

  #pragma unroll
  for (int mt=0; mt<2; mt++){
    int y = y0 + wm*32 + mt*16 + qr;
    #pragma unroll
    for (int nt=0; nt<8; nt++){
      int e = e0 + wn*64 + nt*8 + qc;
      float* po = out + (size_t)y*NOUT + e;
      if (e   < NOUT){ po[0] = acc[mt][nt][0]; po[(size_t)8*NOUT] = acc[mt][nt][2]; }
      if (e+1 < NOUT){ po[1] = acc[mt][nt][1]; po[(size_t)8*NOUT+1] = acc[mt][nt][3]; }
    }
  }
}

// ---------------------------------------------------------------------------
extern "C" void kernel_launch(void* const* d_in, const int* in_sizes, int n_in,
                              void* d_out, int out_size){
  const float* adj_in  = (const float*)d_in[0];
  const float* adj_out = (const float*)d_in[1];
  const float* maskp   = (const float*)d_in[2];
  const int*   item    = (const int*)d_in[3];
  const int*   alias   = (const int*)d_in[4];
  int o = (n_in >= 20 && in_sizes[5] == 1) ? 6 : 5;
  const float* emb   = (const float*)d_in[o+0];
  const float* W_in  = (const float*)d_in[o+1];
  const float* b_in  = (const float*)d_in[o+2];
  const float* W_out = (const float*)d_in[o+3];
  const float* b_out = (const float*)d_in[o+4];
  const float* Ggate = (const float*)d_in[o+5];
  const float* gb    = (const float*)d_in[o+6];
  const float* Gcand = (const float*)d_in[o+7];
  const float* cb    = (const float*)d_in[o+8];
  const float* w1    = (const float*)d_in[o+9];
  const float* w2    = (const float*)d_in[o+10];
  const float* vv    = (const float*)d_in[o+11];
  const float* nb    = (const float*)d_in[o+12];
  const float* Bmat  = (const float*)d_in[o+13];
  float* out = (float*)d_out;
  (void)out_size;

  float* sc = nullptr;
  cudaGetSymbolAddress((void**)&sc, g_scratch);
  __nv_bfloat16 *whi=nullptr, *wlo=nullptr;
  cudaGetSymbolAddress((void**)&whi, g_whi);
  cudaGetSymbolAddress((void**)&wlo, g_wlo);

  float* z     = sc + OFF_Z;
  float* hio   = sc + OFF_HIO;
  float* gates = sc + OFF_GATES;
  float* remb  = sc + OFF_REMB;
  float* seqh  = sc + OFF_SEQH;
  float* seq   = sc + OFF_SEQ;
  float* lasth = sc + OFF_LASTH;
  float* lastT = sc + OFF_LAST;
  float* ma    = sc + OFF_MA;
  float* y1    = sc + OFF_Y1;
  float* bio   = sc + OFF_BIO;

  cudaFuncSetAttribute(k_adj, cudaFuncAttributeMaxDynamicSharedMemorySize, 60000);
  cudaFuncSetAttribute(k_gemm_tc, cudaFuncAttributeMaxDynamicSharedMemorySize, GEMM_SMEM);
  cudaFuncSetAttribute(k_logits_mma, cudaFuncAttributeMaxDynamicSharedMemorySize, LOGITS_SMEM);

  k_prep<<<(172232+255)/256,256>>>(W_in, W_out, Ggate, Gcand, w2, b_in, b_out, whi, wlo, bio);
  k_gather<<<(BT*DIM+255)/256, 256>>>(emb, item, z);
  // hio = [h@W_in+b_in, h@W_out+b_out]   (A = h = z[:,200:300])
  k_gemm_tc<<<dim3(2,200),256,GEMM_SMEM>>>(z+200, nullptr, whi+WO_HIO, wlo+WO_HIO,
                                           bio, hio, 300, 100, 128, 200, 0, 0);
  k_adj<<<BATCH,256,60000>>>(adj_in, adj_out, hio, z);
  // gates = sigmoid(z @ Ggate + gb)
  k_gemm_tc<<<dim3(2,200),256,GEMM_SMEM>>>(z, nullptr, whi+WO_GATE, wlo+WO_GATE,
                                           gb, gates, 300, 300, 320, 200, 0, 1);
  // remb = u*h + (1-u)*tanh([a, r*h] @ Gcand + cb)
  k_gemm_tc<<<dim3(1,200),256,GEMM_SMEM>>>(z, gates, whi+WO_CAND, wlo+WO_CAND,
                                           cb, remb, 300, 300, 320, 100, 1, 3);
  k_seqprep<<<BATCH,128>>>(maskp, alias, remb, seqh, lasth);
  // seq = seqh @ w2
  k_gemm_tc<<<dim3(1,200),256,GEMM_SMEM>>>(seqh, nullptr, whi+WO_SEQ, wlo+WO_SEQ,
                                           nullptr, seq, 100, 100, 128, 100, 0, 0);
  k_sgemm<<<dim3(2,8),256>>>(lasth, w1, nullptr, lastT, 512, DIM, DIM, 0);
  k_attn<<<BATCH,256>>>(lastT, seq, seqh, nb, vv, maskp, ma);
  k_sgemm<<<dim3(2,8),256>>>(ma, Bmat, nullptr, y1, 512, DIM, 200, 0);
  k_logits_mma<<<dim3(EPAD/128, 4), 256, LOGITS_SMEM>>>(emb, y1, out);
}

// round 8
// speedup vs baseline: 1.8036x; 1.1254x over previous
#include <cuda_runtime.h>
#include <cuda_bf16.h>
#include <math.h>
#include <stdint.h>

// ---------------------------------------------------------------------------
// GGNN session-rec, B=512, T=50, D=100, N_NODE=100000, step=1
// R8: adjacency einsums moved to tensor cores (3-term bf16 split, transposed
// B staging); k_gemm_tc pinned to occupancy 2. Everything else as R6.
// ---------------------------------------------------------------------------

#define BATCH 512
#define TSEQ  50
#define DIM   100
#define BT    (BATCH*TSEQ)      /* 25600 */
#define NOUT  99999
#define EPAD  100096            /* 782*128 */

__device__ float g_scratch[26000000];
__device__ __nv_bfloat16 g_whi[172032];
__device__ __nv_bfloat16 g_wlo[172032];

#define WO_HIO  0        /* 256 x 128 */
#define WO_GATE 32768    /* 256 x 320 */
#define WO_CAND 114688   /* 128 x 320 */
#define WO_SEQ  155648   /* 128 x 128 */

#define OFF_Z     0
#define OFF_HIO   7680000
#define OFF_GATES 12800000
#define OFF_REMB  17920000
#define OFF_SEQH  20480000
#define OFF_SEQ   23040000
#define OFF_LASTH 25600000
#define OFF_LAST  25651200
#define OFF_MA    25702400
#define OFF_Y1    25804800
#define OFF_BIO   25856000

__device__ __forceinline__ float sigmoidf_(float x){ return 1.f/(1.f+expf(-x)); }

__device__ __forceinline__ uint32_t pack_bf2(__nv_bfloat16 a, __nv_bfloat16 b){
  return ((uint32_t)__bfloat16_as_ushort(b)<<16) | (uint32_t)__bfloat16_as_ushort(a);
}
__device__ __forceinline__ void split4(float4 v, uint2& hi, uint2& lo){
  __nv_bfloat16 h0=__float2bfloat16(v.x), h1=__float2bfloat16(v.y),
                h2=__float2bfloat16(v.z), h3=__float2bfloat16(v.w);
  hi.x = pack_bf2(h0,h1); hi.y = pack_bf2(h2,h3);
  __nv_bfloat16 l0=__float2bfloat16(v.x-__bfloat162float(h0));
  __nv_bfloat16 l1=__float2bfloat16(v.y-__bfloat162float(h1));
  __nv_bfloat16 l2=__float2bfloat16(v.z-__bfloat162float(h2));
  __nv_bfloat16 l3=__float2bfloat16(v.w-__bfloat162float(h3));
  lo.x = pack_bf2(l0,l1); lo.y = pack_bf2(l2,l3);
}
__device__ __forceinline__ void split1(float v, __nv_bfloat16& h, __nv_bfloat16& l){
  h = __float2bfloat16(v);
  l = __float2bfloat16(v - __bfloat162float(h));
}
__device__ __forceinline__ void mma16816(float* d, uint32_t a0, uint32_t a1,
                                         uint32_t a2, uint32_t a3,
                                         uint32_t b0, uint32_t b1){
  asm volatile("mma.sync.aligned.m16n8k16.row.col.f32.bf16.bf16.f32 "
               "{%0,%1,%2,%3}, {%4,%5,%6,%7}, {%8,%9}, {%0,%1,%2,%3};"
               : "+f"(d[0]), "+f"(d[1]), "+f"(d[2]), "+f"(d[3])
               : "r"(a0), "r"(a1), "r"(a2), "r"(a3), "r"(b0), "r"(b1));
}
__device__ __forceinline__ uint32_t lds32(const __nv_bfloat16* p){
  return *(const uint32_t*)p;
}

// --------------------------- weight prep (one launch) ----------------------
__global__ void k_prep(const float* __restrict__ W_in, const float* __restrict__ W_out,
                       const float* __restrict__ Ggate, const float* __restrict__ Gcand,
                       const float* __restrict__ w2,
                       const float* __restrict__ b_in, const float* __restrict__ b_out,
                       __nv_bfloat16* __restrict__ whi, __nv_bfloat16* __restrict__ wlo,
                       float* __restrict__ bio){
  int i = blockIdx.x*256 + threadIdx.x;
  if (i < 172032){
    float v = 0.f;
    if (i < 32768){
      int n = i>>7, k = i&127;
      if (k < 100) v = (n < 100) ? W_in[k*100+n] : W_out[k*100+(n-100)];
    } else if (i < 114688){
      int j = i-32768; int n = j/320, k = j - n*320;
      if (k < 300) v = Ggate[k*200+n];
    } else if (i < 155648){
      int j = i-114688; int n = j/320, k = j - n*320;
      if (k < 300) v = Gcand[k*100+n];
    } else {
      int j = i-155648; int n = j>>7, k = j&127;
      if (k < 100) v = w2[k*100+n];
    }
    __nv_bfloat16 h = __float2bfloat16(v);
    whi[i] = h;
    wlo[i] = __float2bfloat16(v - __bfloat162float(h));
  } else if (i < 172232){
    int j = i-172032;
    bio[j] = (j < 100) ? b_in[j] : b_out[j-100];
  }
}

// --------------------------- gather: h -> z[:,200:300] ---------------------
__global__ void k_gather(const float* __restrict__ emb, const int* __restrict__ item,
                         float* __restrict__ z){
  int i = blockIdx.x*256 + threadIdx.x;
  if (i >= BT*DIM) return;
  int row = i/DIM, col = i - row*DIM;
  z[row*300 + 200 + col] = __ldg(&emb[(size_t)item[row]*DIM + col]);
}

// --------------------------- adjacency einsums on tensor cores -------------
// per CTA: batch b. a = adj(50x50) @ h(50x100) for in/out halves of hio.
// A tiles: adj 64x64 (t x s) hi/lo; B tiles: hio^T 128x64 (d x s) hi/lo.
// stride 72 bf16 -> conflict-free fragment LDS. 3-term split.
#define AS 72
// smem bf16-unit offsets
#define ADJ_AIH 0
#define ADJ_AIL (64*AS)
#define ADJ_AOH (2*64*AS)
#define ADJ_AOL (3*64*AS)
#define ADJ_BIH (4*64*AS)
#define ADJ_BIL (4*64*AS + 128*AS)
#define ADJ_BOH (4*64*AS + 2*128*AS)
#define ADJ_BOL (4*64*AS + 3*128*AS)
#define ADJ_SMEM_UNITS (4*64*AS + 4*128*AS)         /* 55296 bf16 */
#define ADJ_SMEM_BYTES (ADJ_SMEM_UNITS*2)           /* 110592 B */

__global__ void __launch_bounds__(256, 2) k_adj_tc(
    const float* __restrict__ adj_in, const float* __restrict__ adj_out,
    const float* __restrict__ hio, float* __restrict__ z){
  extern __shared__ __nv_bfloat16 sma[];
  int b = blockIdx.x, tid = threadIdx.x;

  // zero-fill (padding rows/cols must be 0)
  for (int i = tid; i < ADJ_SMEM_UNITS/8; i += 256)
    ((uint4*)sma)[i] = make_uint4(0,0,0,0);
  __syncthreads();

  // stage adj (t x s), split
  for (int i = tid; i < 2500; i += 256){
    int t = i/50, s = i - t*50;
    __nv_bfloat16 h, l;
    split1(__ldg(&adj_in[(size_t)b*2500 + i]), h, l);
    sma[ADJ_AIH + t*AS + s] = h; sma[ADJ_AIL + t*AS + s] = l;
    split1(__ldg(&adj_out[(size_t)b*2500 + i]), h, l);
    sma[ADJ_AOH + t*AS + s] = h; sma[ADJ_AOL + t*AS + s] = l;
  }
  // stage hio transposed: B[d][s] = hio[b*50+s][d]; coalesced global reads
  for (int i = tid; i < 10000; i += 256){
    int s = i/200, d = i - s*200;
    __nv_bfloat16 h, l;
    split1(hio[(size_t)(b*TSEQ + s)*200 + d], h, l);
    if (d < 100){
      sma[ADJ_BIH + d*AS + s] = h; sma[ADJ_BIL + d*AS + s] = l;
    } else {
      sma[ADJ_BOH + (d-100)*AS + s] = h; sma[ADJ_BOL + (d-100)*AS + s] = l;
    }
  }
  __syncthreads();

  int wid = tid>>5, lane = tid&31;
  int e  = wid>>2;            // 0 = a_in, 1 = a_out
  int n0 = (wid&3)*32;        // 32 d-cols per warp
  int qr = lane>>2, qc = (lane&3)*2;

  const __nv_bfloat16* Ah = sma + (e ? ADJ_AOH : ADJ_AIH);
  const __nv_bfloat16* Al = sma + (e ? ADJ_AOL : ADJ_AIL);
  const __nv_bfloat16* Bh = sma + (e ? ADJ_BOH : ADJ_BIH);
  const __nv_bfloat16* Bl = sma + (e ? ADJ_BOL : ADJ_BIL);

  float acc[4][4][4];
  #pragma unroll
  for (int mt=0;mt<4;mt++)
    #pragma unroll
    for (int nt=0;nt<4;nt++)
      #pragma unroll
      for (int j=0;j<4;j++) acc[mt][nt][j]=0.f;

  #pragma unroll
  for (int ks=0; ks<4; ks++){
    int kk = ks*16 + qc;
    uint32_t ah[4][4], al[4][4];
    #pragma unroll
    for (int mt=0; mt<4; mt++){
      int r = mt*16 + qr;
      ah[mt][0]=lds32(Ah + r*AS + kk);     ah[mt][1]=lds32(Ah + (r+8)*AS + kk);
      ah[mt][2]=lds32(Ah + r*AS + kk+8);   ah[mt][3]=lds32(Ah + (r+8)*AS + kk+8);
      al[mt][0]=lds32(Al + r*AS + kk);     al[mt][1]=lds32(Al + (r+8)*AS + kk);
      al[mt][2]=lds32(Al + r*AS + kk+8);   al[mt][3]=lds32(Al + (r+8)*AS + kk+8);
    }
    #pragma unroll
    for (int nt=0; nt<4; nt++){
      int n = n0 + nt*8 + qr;
      uint32_t bh0 = lds32(Bh + n*AS + kk), bh1 = lds32(Bh + n*AS + kk+8);
      uint32_t bl0 = lds32(Bl + n*AS + kk), bl1 = lds32(Bl + n*AS + kk+8);
      #pragma unroll
      for (int mt=0; mt<4; mt++){
        mma16816(acc[mt][nt], ah[mt][0],ah[mt][1],ah[mt][2],ah[mt][3], bh0,bh1);
        mma16816(acc[mt][nt], al[mt][0],al[mt][1],al[mt][2],al[mt][3], bh0,bh1);
        mma16816(acc[mt][nt], ah[mt][0],ah[mt][1],ah[mt][2],ah[mt][3], bl0,bl1);
      }
    }
  }

  // epilogue: z[(b*50+t)*300 + e*100 + d], t<50, d<100
  int cb = e*100;
  #pragma unroll
  for (int mt=0; mt<4; mt++){
    int t0 = mt*16 + qr;
    #pragma unroll
    for (int nt=0; nt<4; nt++){
      int d = n0 + nt*8 + qc;
      if (d+1 < 100){
        if (t0 < TSEQ){
          float* p = z + (size_t)(b*TSEQ+t0)*300 + cb + d;
          p[0] = acc[mt][nt][0]; p[1] = acc[mt][nt][1];
        }
        if (t0+8 < TSEQ){
          float* p = z + (size_t)(b*TSEQ+t0+8)*300 + cb + d;
          p[0] = acc[mt][nt][2]; p[1] = acc[mt][nt][3];
        }
      }
    }
  }
}

// --------------------------- small FFMA SGEMM ------------------------------
__global__ void k_sgemm(const float* __restrict__ A, const float* __restrict__ Bm,
                        const float* __restrict__ bias, float* __restrict__ C,
                        int M, int N, int K, int act){
  __shared__ float As[16][65];
  __shared__ float Bs[16][65];
  int tid = threadIdx.x;
  int tx = tid & 15, ty = tid >> 4;
  int m0 = blockIdx.y*64, n0 = blockIdx.x*64;
  float acc[4][4] = {};
  for (int k0=0;k0<K;k0+=16){
    for (int idx=tid; idx<1024; idx+=256){
      int m = idx>>4, k = idx&15;
      As[k][m] = (k0+k < K) ? A[(size_t)(m0+m)*K + k0+k] : 0.f;
    }
    for (int idx=tid; idx<1024; idx+=256){
      int k = idx>>6, n = idx&63;
      Bs[k][n] = (k0+k < K && n0+n < N) ? Bm[(size_t)(k0+k)*N + n0+n] : 0.f;
    }
    __syncthreads();
    #pragma unroll
    for (int kk=0;kk<16;kk++){
      float a[4], bb[4];
      #pragma unroll
      for (int i=0;i<4;i++) a[i] = As[kk][ty+16*i];
      #pragma unroll
      for (int j=0;j<4;j++) bb[j] = Bs[kk][tx+16*j];
      #pragma unroll
      for (int i=0;i<4;i++)
        #pragma unroll
        for (int j=0;j<4;j++)
          acc[i][j] += a[i]*bb[j];
    }
    __syncthreads();
  }
  #pragma unroll
  for (int j=0;j<4;j++){
    int n = n0 + tx + 16*j;
    if (n >= N) continue;
    float bv = bias ? bias[n] : 0.f;
    #pragma unroll
    for (int i=0;i<4;i++){
      int m = m0 + ty + 16*i;
      float v = acc[i][j] + bv;
      if (act==1)      v = sigmoidf_(v);
      else if (act==2) v = tanhf(v);
      C[(size_t)m*N + n] = v;
    }
  }
}

// --------------------------- seq_h / last_h gather -------------------------
__global__ void k_seqprep(const float* __restrict__ mask, const int* __restrict__ alias,
                          const float* __restrict__ remb,
                          float* __restrict__ seqh, float* __restrict__ lasth){
  __shared__ int al[TSEQ];
  __shared__ int lid_s;
  int b = blockIdx.x, tid = threadIdx.x;
  if (tid < TSEQ) al[tid] = alias[b*TSEQ+tid];
  __syncthreads();
  if (tid == 0){
    float s = 0.f;
    for (int t=0;t<TSEQ;t++) s += mask[b*TSEQ+t];
    int r = (int)(s + 0.5f) - 1;
    if (r < 0) r = 0; if (r >= TSEQ) r = TSEQ-1;
    lid_s = al[r];
  }
  __syncthreads();
  for (int i=tid;i<TSEQ*DIM;i+=128){
    int t = i/DIM, j = i - t*DIM;
    seqh[(size_t)(b*TSEQ+t)*DIM + j] = remb[(size_t)(b*TSEQ + al[t])*DIM + j];
  }
  if (tid < DIM) lasth[b*DIM+tid] = remb[(size_t)(b*TSEQ + lid_s)*DIM + tid];
}

// --------------------------- attention readout -----------------------------
__global__ void k_attn(const float* __restrict__ last, const float* __restrict__ seq,
                       const float* __restrict__ seqh, const float* __restrict__ nb,
                       const float* __restrict__ v, const float* __restrict__ mask,
                       float* __restrict__ ma){
  __shared__ float coef[TSEQ], ls[DIM], vs[DIM], bs[DIM];
  int b = blockIdx.x, tid = threadIdx.x;
  if (tid < DIM){ ls[tid]=last[b*DIM+tid]; vs[tid]=v[tid]; bs[tid]=nb[tid]; }
  __syncthreads();
  int w = tid >> 5, lane = tid & 31;
  for (int t=w; t<TSEQ; t+=8){
    const float* srow = seq + (size_t)(b*TSEQ+t)*DIM;
    float p = 0.f;
    for (int j=lane; j<DIM; j+=32){
      float mv = sigmoidf_(ls[j]+srow[j]+bs[j]);
      p += mv*vs[j];
    }
    #pragma unroll
    for (int o=16;o;o>>=1) p += __shfl_xor_sync(0xffffffffu, p, o);
    if (lane==0) coef[t] = p * mask[b*TSEQ+t];
  }
  __syncthreads();
  if (tid < DIM){
    float s = 0.f;
    #pragma unroll
    for (int t=0;t<TSEQ;t++) s += coef[t]*seqh[(size_t)(b*TSEQ+t)*DIM+tid];
    ma[b*200+tid]       = s;
    ma[b*200+100+tid]   = ls[tid];
  }
}

// --------------------------- generic tc GEMM (inline A split) --------------
#define LS2 72
#define GEMM_SMEM (4*128*LS2*2)   /* 73728 */

__global__ void __launch_bounds__(256, 2) k_gemm_tc(
    const float* __restrict__ A, const float* __restrict__ Gt,
    const __nv_bfloat16* __restrict__ Whi, const __nv_bfloat16* __restrict__ Wlo,
    const float* __restrict__ bias, float* __restrict__ C,
    int Astride, int Ka, int Kp, int Nact, int amode, int emode){
  extern __shared__ __nv_bfloat16 smg[];
  __nv_bfloat16* sAh = smg;
  __nv_bfloat16* sAl = smg + 128*LS2;
  __nv_bfloat16* sWh = smg + 2*128*LS2;
  __nv_bfloat16* sWl = smg + 3*128*LS2;
  int tid = threadIdx.x;
  int n0 = blockIdx.x*128, y0 = blockIdx.y*128;
  int wid = tid>>5, lane = tid&31;
  int wm = wid&3, wn = wid>>2;
  int qr = lane>>2, qc = (lane&3)*2;

  float acc[2][8][4];
  #pragma unroll
  for (int mt=0;mt<2;mt++)
    #pragma unroll
    for (int nt=0;nt<8;nt++)
      #pragma unroll
      for (int j=0;j<4;j++) acc[mt][nt][j]=0.f;

  int nchunk = Kp >> 6;
  for (int kc=0; kc<nchunk; kc++){
    #pragma unroll
    for (int s=0;s<8;s++){
      int idx = s*256+tid;
      int row = idx>>4, q = idx&15;
      int col = kc*64 + q*4;
      float4 v = make_float4(0.f,0.f,0.f,0.f);
      if (amode == 0){
        if (col < Ka) v = *(const float4*)(A + (size_t)(y0+row)*Astride + col);
      } else {
        if (col < 200) v = *(const float4*)(A + (size_t)(y0+row)*300 + col);
        else if (col < 300){
          float4 zv = *(const float4*)(A + (size_t)(y0+row)*300 + col);
          float4 gv = *(const float4*)(Gt + (size_t)(y0+row)*200 + (col-200));
          v = make_float4(zv.x*gv.x, zv.y*gv.y, zv.z*gv.z, zv.w*gv.w);
        }
      }
      uint2 hi, lo; split4(v, hi, lo);
      *(uint2*)(sAh + row*LS2 + q*4) = hi;
      *(uint2*)(sAl + row*LS2 + q*4) = lo;
    }
    #pragma unroll
    for (int s=0;s<4;s++){
      int idx = s*256+tid;
      int row = idx>>3, c8 = idx&7;
      size_t g = (size_t)(n0+row)*Kp + kc*64 + c8*8;
      *(uint4*)(sWh + row*LS2 + c8*8) = *(const uint4*)(Whi + g);
      *(uint4*)(sWl + row*LS2 + c8*8) = *(const uint4*)(Wlo + g);
    }
    __syncthreads();
    #pragma unroll
    for (int ks=0; ks<4; ks++){
      int kk = ks*16 + qc;
      uint32_t ah[2][4], al[2][4];
      #pragma unroll
      for (int mt=0; mt<2; mt++){
        int r = wm*32 + mt*16 + qr;
        const __nv_bfloat16* p0h = sAh + r*LS2;
        const __nv_bfloat16* p1h = sAh + (r+8)*LS2;
        const __nv_bfloat16* p0l = sAl + r*LS2;
        const __nv_bfloat16* p1l = sAl + (r+8)*LS2;
        ah[mt][0]=lds32(p0h+kk); ah[mt][1]=lds32(p1h+kk);
        ah[mt][2]=lds32(p0h+kk+8); ah[mt][3]=lds32(p1h+kk+8);
        al[mt][0]=lds32(p0l+kk); al[mt][1]=lds32(p1l+kk);
        al[mt][2]=lds32(p0l+kk+8); al[mt][3]=lds32(p1l+kk+8);
      }
      #pragma unroll
      for (int nt=0; nt<8; nt++){
        int n = wn*64 + nt*8 + qr;
        const __nv_bfloat16* pbh = sWh + n*LS2 + kk;
        const __nv_bfloat16* pbl = sWl + n*LS2 + kk;
        uint32_t bh0 = lds32(pbh), bh1 = lds32(pbh+8);
        uint32_t bl0 = lds32(pbl), bl1 = lds32(pbl+8);
        #pragma unroll
        for (int mt=0; mt<2; mt++){
          mma16816(acc[mt][nt], ah[mt][0],ah[mt][1],ah[mt][2],ah[mt][3], bh0,bh1);
          mma16816(acc[mt][nt], al[mt][0],al[mt][1],al[mt][2],al[mt][3], bh0,bh1);
          mma16816(acc[mt][nt], ah[mt][0],ah[mt][1],ah[mt][2],ah[mt][3], bl0,bl1);
        }
      }
    }
    __syncthreads();
  }

  #pragma unroll
  for (int mt=0; mt<2; mt++){
    int y = y0 + wm*32 + mt*16 + qr;
    #pragma unroll
    for (int nt=0; nt<8; nt++){
      #pragma unroll
      for (int half=0; half<2; half++){
        int nn = n0 + wn*64 + nt*8 + qc + half;
        if (nn >= Nact) continue;
        float bv = bias ? bias[nn] : 0.f;
        float v0 = acc[mt][nt][half]   + bv;
        float v1 = acc[mt][nt][2+half] + bv;
        if (emode==1){ v0 = sigmoidf_(v0); v1 = sigmoidf_(v1); }
        else if (emode==3){
          v0 = tanhf(v0); v1 = tanhf(v1);
          float u0 = Gt[(size_t)y*200 + 100 + nn];
          float u1 = Gt[(size_t)(y+8)*200 + 100 + nn];
          float h0 = A[(size_t)y*300 + 200 + nn];
          float h1 = A[(size_t)(y+8)*300 + 200 + nn];
          v0 = u0*h0 + (1.f-u0)*v0;
          v1 = u1*h1 + (1.f-u1)*v1;
        }
        C[(size_t)y*Nact + nn] = v0;
        C[(size_t)(y+8)*Nact + nn] = v1;
      }
    }
  }
}

// --------------------------- logits GEMM (inline both operands) ------------
#define LOGITS_SMEM (4*128*LS2*2)   /* 73728 */

__global__ void __launch_bounds__(256, 2) k_logits_mma(
    const float* __restrict__ emb, const float* __restrict__ y1,
    float* __restrict__ out){
  extern __shared__ __nv_bfloat16 smb[];
  __nv_bfloat16* sYh = smb;
  __nv_bfloat16* sYl = smb + 128*LS2;
  __nv_bfloat16* sEh = smb + 2*128*LS2;
  __nv_bfloat16* sEl = smb + 3*128*LS2;

  int tid = threadIdx.x;
  int e0 = blockIdx.x*128;
  int y0 = blockIdx.y*128;
  int wid = tid>>5, lane = tid&31;
  int wm = wid&3, wn = wid>>2;
  int qr = lane>>2, qc = (lane&3)*2;

  float acc[2][8][4];
  #pragma unroll
  for (int mt=0;mt<2;mt++)
    #pragma unroll
    for (int nt=0;nt<8;nt++)
      #pragma unroll
      for (int j=0;j<4;j++) acc[mt][nt][j] = 0.f;

  #pragma unroll
  for (int kc=0; kc<2; kc++){
    #pragma unroll
    for (int s=0;s<8;s++){
      int idx = s*256+tid;
      int row = idx>>4, q = idx&15;
      int col = kc*64 + q*4;
      float4 vy = make_float4(0.f,0.f,0.f,0.f);
      if (col < 100) vy = *(const float4*)(y1 + (size_t)(y0+row)*100 + col);
      uint2 hi, lo; split4(vy, hi, lo);
      *(uint2*)(sYh + row*LS2 + q*4) = hi;
      *(uint2*)(sYl + row*LS2 + q*4) = lo;
      float4 ve = make_float4(0.f,0.f,0.f,0.f);
      int er = e0 + row;
      if (col < 100 && er < NOUT) ve = *(const float4*)(emb + (size_t)(er+1)*100 + col);
      split4(ve, hi, lo);
      *(uint2*)(sEh + row*LS2 + q*4) = hi;
      *(uint2*)(sEl + row*LS2 + q*4) = lo;
    }
    __syncthreads();
    #pragma unroll
    for (int ks=0; ks<4; ks++){
      int kk = ks*16 + qc;
      uint32_t ah[2][4], al[2][4];
      #pragma unroll
      for (int mt=0; mt<2; mt++){
        int r = wm*32 + mt*16 + qr;
        const __nv_bfloat16* p0h = sYh + r*LS2;
        const __nv_bfloat16* p1h = sYh + (r+8)*LS2;
        const __nv_bfloat16* p0l = sYl + r*LS2;
        const __nv_bfloat16* p1l = sYl + (r+8)*LS2;
        ah[mt][0]=lds32(p0h+kk); ah[mt][1]=lds32(p1h+kk);
        ah[mt][2]=lds32(p0h+kk+8); ah[mt][3]=lds32(p1h+kk+8);
        al[mt][0]=lds32(p0l+kk); al[mt][1]=lds32(p1l+kk);
        al[mt][2]=lds32(p0l+kk+8); al[mt][3]=lds32(p1l+kk+8);
      }
      #pragma unroll
      for (int nt=0; nt<8; nt++){
        int n = wn*64 + nt*8 + qr;
        const __nv_bfloat16* pbh = sEh + n*LS2 + kk;
        const __nv_bfloat16* pbl = sEl + n*LS2 + kk;
        uint32_t bh0 = lds32(pbh), bh1 = lds32(pbh+8);
        uint32_t bl0 = lds32(pbl), bl1 = lds32(pbl+8);
        #pragma unroll
        for (int mt=0; mt<2; mt++){
          mma16816(acc[mt][nt], ah[mt][0],ah[mt][1],ah[mt][2],ah[mt][3], bh0,bh1);
          mma16816(acc[mt][nt], al[mt][0],al[mt][1],al[mt][2],al[mt][3], bh0,bh1);
          mma16816(acc[mt][nt], ah[mt][0],ah[mt][1],ah[mt][2],ah[mt][3], bl0,bl1);
        }
      }
    }
    __syncthreads();
  }

  #pragma unroll
  for (int mt=0; mt<2; mt++){
    int y = y0 + wm*32 + mt*16 + qr;
    #pragma unroll
    for (int nt=0; nt<8; nt++){
      int e = e0 + wn*64 + nt*8 + qc;
      float* po = out + (size_t)y*NOUT + e;
      if (e   < NOUT){ po[0] = acc[mt][nt][0]; po[(size_t)8*NOUT] = acc[mt][nt][2]; }
      if (e+1 < NOUT){ po[1] = acc[mt][nt][1]; po[(size_t)8*NOUT+1] = acc[mt][nt][3]; }
    }
  }
}

// ---------------------------------------------------------------------------
extern "C" void kernel_launch(void* const* d_in, const int* in_sizes, int n_in,
                              void* d_out, int out_size){
  const float* adj_in  = (const float*)d_in[0];
  const float* adj_out = (const float*)d_in[1];
  const float* maskp   = (const float*)d_in[2];
  const int*   item    = (const int*)d_in[3];
  const int*   alias   = (const int*)d_in[4];
  int o = (n_in >= 20 && in_sizes[5] == 1) ? 6 : 5;
  const float* emb   = (const float*)d_in[o+0];
  const float* W_in  = (const float*)d_in[o+1];
  const float* b_in  = (const float*)d_in[o+2];
  const float* W_out = (const float*)d_in[o+3];
  const float* b_out = (const float*)d_in[o+4];
  const float* Ggate = (const float*)d_in[o+5];
  const float* gb    = (const float*)d_in[o+6];
  const float* Gcand = (const float*)d_in[o+7];
  const float* cb    = (const float*)d_in[o+8];
  const float* w1    = (const float*)d_in[o+9];
  const float* w2    = (const float*)d_in[o+10];
  const float* vv    = (const float*)d_in[o+11];
  const float* nb    = (const float*)d_in[o+12];
  const float* Bmat  = (const float*)d_in[o+13];
  float* out = (float*)d_out;
  (void)out_size;

  float* sc = nullptr;
  cudaGetSymbolAddress((void**)&sc, g_scratch);
  __nv_bfloat16 *whi=nullptr, *wlo=nullptr;
  cudaGetSymbolAddress((void**)&whi, g_whi);
  cudaGetSymbolAddress((void**)&wlo, g_wlo);

  float* z     = sc + OFF_Z;
  float* hio   = sc + OFF_HIO;
  float* gates = sc + OFF_GATES;
  float* remb  = sc + OFF_REMB;
  float* seqh  = sc + OFF_SEQH;
  float* seq   = sc + OFF_SEQ;
  float* lasth = sc + OFF_LASTH;
  float* lastT = sc + OFF_LAST;
  float* ma    = sc + OFF_MA;
  float* y1    = sc + OFF_Y1;
  float* bio   = sc + OFF_BIO;

  cudaFuncSetAttribute(k_adj_tc, cudaFuncAttributeMaxDynamicSharedMemorySize, ADJ_SMEM_BYTES);
  cudaFuncSetAttribute(k_gemm_tc, cudaFuncAttributeMaxDynamicSharedMemorySize, GEMM_SMEM);
  cudaFuncSetAttribute(k_logits_mma, cudaFuncAttributeMaxDynamicSharedMemorySize, LOGITS_SMEM);

  k_prep<<<(172232+255)/256,256>>>(W_in, W_out, Ggate, Gcand, w2, b_in, b_out, whi, wlo, bio);
  k_gather<<<(BT*DIM+255)/256, 256>>>(emb, item, z);
  // hio = [h@W_in+b_in, h@W_out+b_out]   (A = h = z[:,200:300])
  k_gemm_tc<<<dim3(2,200),256,GEMM_SMEM>>>(z+200, nullptr, whi+WO_HIO, wlo+WO_HIO,
                                           bio, hio, 300, 100, 128, 200, 0, 0);
  k_adj_tc<<<BATCH,256,ADJ_SMEM_BYTES>>>(adj_in, adj_out, hio, z);
  // gates = sigmoid(z @ Ggate + gb)
  k_gemm_tc<<<dim3(2,200),256,GEMM_SMEM>>>(z, nullptr, whi+WO_GATE, wlo+WO_GATE,
                                           gb, gates, 300, 300, 320, 200, 0, 1);
  // remb = u*h + (1-u)*tanh([a, r*h] @ Gcand + cb)
  k_gemm_tc<<<dim3(1,200),256,GEMM_SMEM>>>(z, gates, whi+WO_CAND, wlo+WO_CAND,
                                           cb, remb, 300, 300, 320, 100, 1, 3);
  k_seqprep<<<BATCH,128>>>(maskp, alias, remb, seqh, lasth);
  // seq = seqh @ w2
  k_gemm_tc<<<dim3(1,200),256,GEMM_SMEM>>>(seqh, nullptr, whi+WO_SEQ, wlo+WO_SEQ,
                                           nullptr, seq, 100, 100, 128, 100, 0, 0);
  k_sgemm<<<dim3(2,8),256>>>(lasth, w1, nullptr, lastT, 512, DIM, DIM, 0);
  k_attn<<<BATCH,256>>>(lastT, seq, seqh, nb, vv, maskp, ma);
  k_sgemm<<<dim3(2,8),256>>>(ma, Bmat, nullptr, y1, 512, DIM, 200, 0);
  k_logits_mma<<<dim3(EPAD/128, 4), 256, LOGITS_SMEM>>>(emb, y1, out);
}